// round 2
// baseline (speedup 1.0000x reference)
#include <cuda_runtime.h>
#include <math.h>

#define NN   20000
#define EE   100000
#define F1   167
#define HIDD 1024
#define EDK  10     // edge feature dims used in We
#define EAC  12     // edge_attr columns

// ---------------- scratch (device globals; no allocation allowed) ----------
__device__ float g_hn [(size_t)NN * HIDD];
__device__ float g_lin[(size_t)NN * HIDD];
__device__ float g_hg [(size_t)NN * HIDD];
__device__ float g_h  [(size_t)NN * HIDD];
__device__ float g_logw[(size_t)EE * 4];
__device__ float g_ssrc[(size_t)NN * 4];
__device__ float g_sdst[(size_t)NN * 4];
__device__ float g_s1[HIDD];
__device__ float g_s2[HIDD];
__device__ float g_scale[HIDD];
__device__ float g_shift[HIDD];
__device__ float g_ve[EDK * 4];
__device__ int   g_deg[NN];
__device__ int   g_off[NN + 1];
__device__ int   g_cur[NN];
__device__ int   g_eid[EE];

// ---------------- utility kernels ----------------
__global__ void k_zero_f(float* p, int n) {
    int i = blockIdx.x * blockDim.x + threadIdx.x;
    if (i < n) p[i] = 0.f;
}
__global__ void k_zero_i(int* p, int n) {
    int i = blockIdx.x * blockDim.x + threadIdx.x;
    if (i < n) p[i] = 0;
}

// ---------------- CSR build ----------------
__global__ void k_hist(const int* __restrict__ dst, int* __restrict__ deg) {
    int e = blockIdx.x * blockDim.x + threadIdx.x;
    if (e < EE) atomicAdd(&deg[dst[e]], 1);
}

__global__ void k_scan(const int* __restrict__ deg, int* __restrict__ off, int n) {
    __shared__ int sh[1024];
    __shared__ int carry;
    int t = threadIdx.x;
    if (t == 0) { carry = 0; off[0] = 0; }
    __syncthreads();
    for (int base = 0; base < n; base += 1024) {
        int v = (base + t < n) ? deg[base + t] : 0;
        sh[t] = v;
        __syncthreads();
        for (int d = 1; d < 1024; d <<= 1) {
            int add = (t >= d) ? sh[t - d] : 0;
            __syncthreads();
            sh[t] += add;
            __syncthreads();
        }
        if (base + t < n) off[base + t + 1] = carry + sh[t];
        __syncthreads();
        if (t == 0) carry += sh[1023];
        __syncthreads();
    }
}

__global__ void k_scatter(const int* __restrict__ dst, const int* __restrict__ off,
                          int* __restrict__ cur, int* __restrict__ eid) {
    int e = blockIdx.x * blockDim.x + threadIdx.x;
    if (e >= EE) return;
    int d = dst[e];
    int p = atomicAdd(&cur[d], 1);
    eid[off[d] + p] = e;
}

// ---------------- BatchNorm ----------------
__global__ void k_bnstat(const float* __restrict__ x, float* __restrict__ s1,
                         float* __restrict__ s2, int F) {
    int c = blockIdx.x * blockDim.x + threadIdx.x;
    if (c >= F) return;
    int nchunks = gridDim.y;
    int chunk = (NN + nchunks - 1) / nchunks;
    int r0 = blockIdx.y * chunk;
    int r1 = r0 + chunk; if (r1 > NN) r1 = NN;
    float a = 0.f, b = 0.f;
    for (int r = r0; r < r1; r++) {
        float v = x[(size_t)r * F + c];
        a += v; b += v * v;
    }
    atomicAdd(&s1[c], a);
    atomicAdd(&s2[c], b);
}

__global__ void k_bnfin(const float* __restrict__ s1, const float* __restrict__ s2,
                        const float* __restrict__ g, const float* __restrict__ b,
                        float* __restrict__ scale, float* __restrict__ shift, int F) {
    int c = blockIdx.x * blockDim.x + threadIdx.x;
    if (c >= F) return;
    float invN = 1.f / (float)NN;
    float mu = s1[c] * invN;
    float var = s2[c] * invN - mu * mu;
    float rstd = rsqrtf(var + 1e-5f);
    float sc = rstd * g[c];
    scale[c] = sc;
    shift[c] = b[c] - mu * sc;
}

__global__ void k_norm(const float* __restrict__ x, const float* __restrict__ scale,
                       const float* __restrict__ shift, float* __restrict__ y,
                       size_t total, int F) {
    size_t i = (size_t)blockIdx.x * blockDim.x + threadIdx.x;
    if (i >= total) return;
    int c = (int)(i % (size_t)F);
    y[i] = x[i] * scale[c] + shift[c];
}

// ---------------- SGEMM: C[MxN] = A[MxK] @ B[KxN], all row-major ----------------
#define BM 128
#define BN 128
#define BK 8
#define TM 8
#define TN 8
__global__ __launch_bounds__(256) void sgemm(int M, int N, int K,
    const float* __restrict__ A, const float* __restrict__ B, float* __restrict__ C)
{
    __shared__ float As[BK][BM];
    __shared__ float Bs[BK][BN];
    int tid = threadIdx.x;
    int brow = blockIdx.y * BM;
    int bcol = blockIdx.x * BN;
    int tx = tid & 15, ty = tid >> 4;
    float acc[TM][TN];
#pragma unroll
    for (int i = 0; i < TM; i++)
#pragma unroll
        for (int j = 0; j < TN; j++) acc[i][j] = 0.f;

    for (int kk = 0; kk < K; kk += BK) {
#pragma unroll
        for (int i = 0; i < 4; i++) {
            int idx = tid + i * 256;
            int ar = idx >> 3, ac = idx & 7;
            int gr = brow + ar, gc = kk + ac;
            float v = 0.f;
            if (gr < M && gc < K) v = A[(size_t)gr * K + gc];
            As[ac][ar] = v;
        }
#pragma unroll
        for (int i = 0; i < 4; i++) {
            int idx = tid + i * 256;
            int br = idx >> 7, bc = idx & 127;
            int gr = kk + br, gc = bcol + bc;
            float v = 0.f;
            if (gr < K && gc < N) v = B[(size_t)gr * N + gc];
            Bs[br][bc] = v;
        }
        __syncthreads();
#pragma unroll
        for (int k = 0; k < BK; k++) {
            float ra[TM], rb[TN];
#pragma unroll
            for (int i = 0; i < TM; i++) ra[i] = As[k][ty * TM + i];
#pragma unroll
            for (int j = 0; j < TN; j++) rb[j] = Bs[k][tx * TN + j];
#pragma unroll
            for (int i = 0; i < TM; i++)
#pragma unroll
                for (int j = 0; j < TN; j++) acc[i][j] += ra[i] * rb[j];
        }
        __syncthreads();
    }
#pragma unroll
    for (int i = 0; i < TM; i++) {
        int gr = brow + ty * TM + i;
        if (gr >= M) continue;
#pragma unroll
        for (int j = 0; j < TN; j++) {
            int gc = bcol + tx * TN + j;
            if (gc < N) C[(size_t)gr * N + gc] = acc[i][j];
        }
    }
}

// ---------------- GAT pieces ----------------
// ve[k,h] = sum_d We[k, h*O+d] * attn[2, h, d]
__global__ void k_ve(const float* __restrict__ We, const float* __restrict__ attn,
                     float* __restrict__ ve, int H, int O) {
    int t = threadIdx.x;
    if (t >= H * EDK) return;
    int h = t / EDK, k = t % EDK;
    const float* a2 = attn + (size_t)(2 * H + h) * O;
    const float* w = We + (size_t)k * H * O + (size_t)h * O;
    float s = 0.f;
    for (int d = 0; d < O; d++) s += w[d] * a2[d];
    ve[k * H + h] = s;
}

// per (n,h): s_src = dot(hg[n,h,:], attn0[h]), s_dst = dot(hg[n,h,:], attn1[h])
__global__ void k_sdots(const float* __restrict__ hg, const float* __restrict__ attn,
                        float* __restrict__ ssrc, float* __restrict__ sdst, int H, int O) {
    int gw = (blockIdx.x * blockDim.x + threadIdx.x) >> 5;
    int lane = threadIdx.x & 31;
    if (gw >= NN * H) return;
    int n = gw / H, h = gw % H;
    const float* hr = hg + (size_t)n * H * O + (size_t)h * O;
    const float* a0 = attn + (size_t)h * O;
    const float* a1 = attn + (size_t)(H + h) * O;
    float d0 = 0.f, d1 = 0.f;
    for (int d = lane; d < O; d += 32) {
        float v = hr[d];
        d0 += v * a0[d];
        d1 += v * a1[d];
    }
#pragma unroll
    for (int s = 16; s; s >>= 1) {
        d0 += __shfl_down_sync(0xFFFFFFFFu, d0, s);
        d1 += __shfl_down_sync(0xFFFFFFFFu, d1, s);
    }
    if (lane == 0) { ssrc[gw] = d0; sdst[gw] = d1; }
}

__global__ void k_logits(const int* __restrict__ ei, const float* __restrict__ ea,
                         const float* __restrict__ ssrc, const float* __restrict__ sdst,
                         const float* __restrict__ ve, const float* __restrict__ at,
                         float* __restrict__ logw, int H) {
    int idx = blockIdx.x * blockDim.x + threadIdx.x;
    if (idx >= EE * H) return;
    int e = idx / H, h = idx % H;
    int s = ei[e], d = ei[EE + e];
    const float* row = ea + (size_t)e * EAC;
    float t = row[0];
    float se = 0.f;
#pragma unroll
    for (int k = 0; k < EDK; k++) se += row[1 + k] * ve[k * H + h];
    float l = ssrc[s * H + h] + sdst[d * H + h] + se + t * at[h];
    logw[idx] = (l > 0.f) ? l : 0.2f * l;
}

// softmax per (dst node, head) via CSR; w written in place over logits
__global__ void k_softmax(const int* __restrict__ off, const int* __restrict__ eid,
                          float* __restrict__ logw, int H) {
    int idx = blockIdx.x * blockDim.x + threadIdx.x;
    if (idx >= NN * H) return;
    int n = idx / H, h = idx % H;
    int d0 = off[n], d1 = off[n + 1];
    if (d0 == d1) return;
    float m = -INFINITY;
    for (int i = d0; i < d1; i++) m = fmaxf(m, logw[eid[i] * H + h]);
    float s = 0.f;
    for (int i = d0; i < d1; i++) {
        float p = expf(logw[eid[i] * H + h] - m);
        logw[eid[i] * H + h] = p;
        s += p;
    }
    float inv = 1.f / (s + 1e-16f);
    for (int i = d0; i < d1; i++) logw[eid[i] * H + h] *= inv;
}

// aggregation + epilogue for H=4, O=256 layers. Block per node, 256 threads.
__global__ __launch_bounds__(256) void k_agg_big(
    const float* __restrict__ hg, const float* __restrict__ w,
    const int* __restrict__ off, const int* __restrict__ eid,
    const float* __restrict__ ea, const int* __restrict__ src,
    const float* __restrict__ We, const float* __restrict__ lin,
    const float* __restrict__ lb, const float* __restrict__ cb,
    float* __restrict__ out)
{
    int n = blockIdx.x;
    int t = threadIdx.x;
    __shared__ float qs[40];   // [h][k]
    if (t < 40) qs[t] = 0.f;
    float acc0 = 0.f, acc1 = 0.f, acc2 = 0.f, acc3 = 0.f;
    int d0 = off[n], d1 = off[n + 1];
    for (int i = d0; i < d1; i++) {
        int e = eid[i];
        int s = src[e];
        float4 wv = *(const float4*)(w + (size_t)e * 4);
        const float* hr = hg + (size_t)s * 1024;
        acc0 += wv.x * hr[t];
        acc1 += wv.y * hr[t + 256];
        acc2 += wv.z * hr[t + 512];
        acc3 += wv.w * hr[t + 768];
        if (t < 40) {
            int h = t / 10, k = t % 10;
            float wh = (h == 0) ? wv.x : (h == 1) ? wv.y : (h == 2) ? wv.z : wv.w;
            qs[t] += wh * ea[(size_t)e * EAC + 1 + k];
        }
    }
    __syncthreads();
    float acch[4] = {acc0, acc1, acc2, acc3};
#pragma unroll
    for (int h = 0; h < 4; h++) {
        int f = h * 256 + t;
        float et = 0.f;
#pragma unroll
        for (int k = 0; k < 10; k++) et += qs[h * 10 + k] * We[k * 1024 + f];
        float v = lin[(size_t)n * 1024 + f] + lb[f] + cb[f] + acch[h] + et;
        out[(size_t)n * 1024 + f] = fmaxf(v, 0.f);
    }
}

// aggregation + epilogue for layer 3 (H=1, O=2). Thread per node.
__global__ void k_agg_small(
    const float* __restrict__ hg, const float* __restrict__ w,
    const int* __restrict__ off, const int* __restrict__ eid,
    const float* __restrict__ ea, const int* __restrict__ src,
    const float* __restrict__ We, const float* __restrict__ lin,
    const float* __restrict__ lb, const float* __restrict__ cb,
    float* __restrict__ out)
{
    int n = blockIdx.x * blockDim.x + threadIdx.x;
    if (n >= NN) return;
    float a0 = 0.f, a1 = 0.f;
    float q[10];
#pragma unroll
    for (int k = 0; k < 10; k++) q[k] = 0.f;
    int d0 = off[n], d1 = off[n + 1];
    for (int i = d0; i < d1; i++) {
        int e = eid[i];
        int s = src[e];
        float wv = w[e];
        a0 += wv * hg[(size_t)s * 2];
        a1 += wv * hg[(size_t)s * 2 + 1];
        const float* row = ea + (size_t)e * EAC;
#pragma unroll
        for (int k = 0; k < 10; k++) q[k] += wv * row[1 + k];
    }
    float e0 = 0.f, e1 = 0.f;
#pragma unroll
    for (int k = 0; k < 10; k++) { e0 += q[k] * We[k * 2]; e1 += q[k] * We[k * 2 + 1]; }
    float v0 = lin[(size_t)n * 2] + lb[0] + cb[0] + a0 + e0;
    float v1 = lin[(size_t)n * 2 + 1] + lb[1] + cb[1] + a1 + e1;
    out[(size_t)n * 2] = fmaxf(v0, 0.f);
    out[(size_t)n * 2 + 1] = fmaxf(v1, 0.f);
}

// ---------------- host driver ----------------
static inline int cdiv(int a, int b) { return (a + b - 1) / b; }

struct Scratch {
    float *hn, *lin, *hg, *h, *logw, *ssrc, *sdst, *s1, *s2, *scale, *shift, *ve;
    int *deg, *off, *cur, *eid;
};

static void run_layer(const Scratch& S, const float* xin, int F, int H, int O,
                      const float* Wg, const float* We, const float* attn,
                      const float* at, const float* cb,
                      const float* lw, const float* lb,
                      const float* g, const float* b,
                      float* out, const int* ei, const float* ea)
{
    int HO = H * O;
    // BatchNorm
    k_zero_f<<<cdiv(F, 256), 256>>>(S.s1, F);
    k_zero_f<<<cdiv(F, 256), 256>>>(S.s2, F);
    k_bnstat<<<dim3(cdiv(F, 256), 40), 256>>>(xin, S.s1, S.s2, F);
    k_bnfin<<<cdiv(F, 256), 256>>>(S.s1, S.s2, g, b, S.scale, S.shift, F);
    size_t tot = (size_t)NN * F;
    k_norm<<<(int)((tot + 255) / 256), 256>>>(xin, S.scale, S.shift, S.hn, tot, F);
    // GEMMs
    dim3 gg(cdiv(HO, BN), cdiv(NN, BM));
    sgemm<<<gg, 256>>>(NN, HO, F, S.hn, lw, S.lin);
    sgemm<<<gg, 256>>>(NN, HO, F, S.hn, Wg, S.hg);
    // attention scalars
    k_ve<<<1, 64>>>(We, attn, S.ve, H, O);
    k_sdots<<<cdiv(NN * H * 32, 256), 256>>>(S.hg, attn, S.ssrc, S.sdst, H, O);
    k_logits<<<cdiv(EE * H, 256), 256>>>(ei, ea, S.ssrc, S.sdst, S.ve, at, S.logw, H);
    k_softmax<<<cdiv(NN * H, 256), 256>>>(S.off, S.eid, S.logw, H);
    // aggregate + epilogue
    if (O == 256) {
        k_agg_big<<<NN, 256>>>(S.hg, S.logw, S.off, S.eid, ea, ei, We, S.lin, lb, cb, out);
    } else {
        k_agg_small<<<cdiv(NN, 256), 256>>>(S.hg, S.logw, S.off, S.eid, ea, ei, We, S.lin, lb, cb, out);
    }
}

extern "C" void kernel_launch(void* const* d_in, const int* in_sizes, int n_in,
                              void* d_out, int out_size)
{
    const float* x  = (const float*)d_in[0];
    const int*   ei = (const int*)d_in[1];
    const float* ea = (const float*)d_in[2];

    const float *Wg[3], *We[3], *attn[3], *at[3], *cb[3];
    const float *lw[3], *lb[3], *gg[3], *bb[3];

    // Two possible input orderings; disambiguate via in_sizes[8]:
    //   signature order: d_in[8] = lw1 (167*1024 = 171008 elems)
    //   dict order:      d_in[8] = Wg2 (1024*1024 = 1048576 elems)
    if (in_sizes[8] == 1048576) {
        // dict-insertion order: all conv params (per layer), then all lin/bn params
        for (int i = 0; i < 3; i++) {
            Wg[i]   = (const float*)d_in[3 + 5 * i];
            We[i]   = (const float*)d_in[4 + 5 * i];
            attn[i] = (const float*)d_in[5 + 5 * i];
            at[i]   = (const float*)d_in[6 + 5 * i];
            cb[i]   = (const float*)d_in[7 + 5 * i];
            lw[i]   = (const float*)d_in[18 + 4 * i];
            lb[i]   = (const float*)d_in[19 + 4 * i];
            gg[i]   = (const float*)d_in[20 + 4 * i];
            bb[i]   = (const float*)d_in[21 + 4 * i];
        }
    } else {
        // reference-signature order: per-layer interleaved
        for (int i = 0; i < 3; i++) {
            Wg[i]   = (const float*)d_in[3 + 9 * i];
            We[i]   = (const float*)d_in[4 + 9 * i];
            attn[i] = (const float*)d_in[5 + 9 * i];
            at[i]   = (const float*)d_in[6 + 9 * i];
            cb[i]   = (const float*)d_in[7 + 9 * i];
            lw[i]   = (const float*)d_in[8 + 9 * i];
            lb[i]   = (const float*)d_in[9 + 9 * i];
            gg[i]   = (const float*)d_in[10 + 9 * i];
            bb[i]   = (const float*)d_in[11 + 9 * i];
        }
    }

    Scratch S;
    cudaGetSymbolAddress((void**)&S.hn, g_hn);
    cudaGetSymbolAddress((void**)&S.lin, g_lin);
    cudaGetSymbolAddress((void**)&S.hg, g_hg);
    cudaGetSymbolAddress((void**)&S.h, g_h);
    cudaGetSymbolAddress((void**)&S.logw, g_logw);
    cudaGetSymbolAddress((void**)&S.ssrc, g_ssrc);
    cudaGetSymbolAddress((void**)&S.sdst, g_sdst);
    cudaGetSymbolAddress((void**)&S.s1, g_s1);
    cudaGetSymbolAddress((void**)&S.s2, g_s2);
    cudaGetSymbolAddress((void**)&S.scale, g_scale);
    cudaGetSymbolAddress((void**)&S.shift, g_shift);
    cudaGetSymbolAddress((void**)&S.ve, g_ve);
    cudaGetSymbolAddress((void**)&S.deg, g_deg);
    cudaGetSymbolAddress((void**)&S.off, g_off);
    cudaGetSymbolAddress((void**)&S.cur, g_cur);
    cudaGetSymbolAddress((void**)&S.eid, g_eid);

    // ---- CSR by destination (built every call; deterministic work) ----
    k_zero_i<<<cdiv(NN, 256), 256>>>(S.deg, NN);
    k_hist<<<cdiv(EE, 256), 256>>>(ei + EE, S.deg);
    k_scan<<<1, 1024>>>(S.deg, S.off, NN);
    k_zero_i<<<cdiv(NN, 256), 256>>>(S.cur, NN);
    k_scatter<<<cdiv(EE, 256), 256>>>(ei + EE, S.off, S.cur, S.eid);

    // ---- 3 layers ----
    run_layer(S, x,   F1,   4, 256, Wg[0], We[0], attn[0], at[0], cb[0], lw[0], lb[0], gg[0], bb[0], S.h, ei, ea);
    run_layer(S, S.h, HIDD, 4, 256, Wg[1], We[1], attn[1], at[1], cb[1], lw[1], lb[1], gg[1], bb[1], S.h, ei, ea);
    run_layer(S, S.h, HIDD, 1, 2,   Wg[2], We[2], attn[2], at[2], cb[2], lw[2], lb[2], gg[2], bb[2], (float*)d_out, ei, ea);
}

// round 5
// speedup vs baseline: 2.1680x; 2.1680x over previous
#include <cuda_runtime.h>
#include <cuda_bf16.h>
#include <cstdint>
#include <math.h>

#define NN   20000
#define EE   100000
#define F1   167
#define HIDD 1024
#define EDK  10
#define EAC  12

// ---------------- scratch (device globals) ----------------
__device__ float g_lin[(size_t)NN * HIDD];
__device__ float g_hg [(size_t)NN * HIDD];
__device__ float g_h  [(size_t)NN * HIDD];
__device__ float g_logw[(size_t)EE * 4];
__device__ float g_ssrc[(size_t)NN * 4];
__device__ float g_sdst[(size_t)NN * 4];
__device__ float g_s1[HIDD];
__device__ float g_s2[HIDD];
__device__ float g_scale[HIDD];
__device__ float g_shift[HIDD];
__device__ float g_ve[EDK * 4];
__device__ int   g_deg[NN];
__device__ int   g_off[NN + 1];
__device__ int   g_cur[NN];
__device__ int   g_eid[EE];
__device__ __nv_bfloat16 g_Ah[(size_t)NN * HIDD];
__device__ __nv_bfloat16 g_Al[(size_t)NN * HIDD];
__device__ __nv_bfloat16 g_B1h[(size_t)HIDD * HIDD];
__device__ __nv_bfloat16 g_B1l[(size_t)HIDD * HIDD];
__device__ __nv_bfloat16 g_B2h[(size_t)HIDD * HIDD];
__device__ __nv_bfloat16 g_B2l[(size_t)HIDD * HIDD];

// ---------------- utility ----------------
__global__ void k_zero_f(float* p, int n) {
    int i = blockIdx.x * blockDim.x + threadIdx.x;
    if (i < n) p[i] = 0.f;
}
__global__ void k_zero_i(int* p, int n) {
    int i = blockIdx.x * blockDim.x + threadIdx.x;
    if (i < n) p[i] = 0;
}

// ---------------- CSR build ----------------
__global__ void k_hist(const int* __restrict__ dst, int* __restrict__ deg) {
    int e = blockIdx.x * blockDim.x + threadIdx.x;
    if (e < EE) atomicAdd(&deg[dst[e]], 1);
}

__global__ void k_scan(const int* __restrict__ deg, int* __restrict__ off, int n) {
    __shared__ int sh[1024];
    __shared__ int carry;
    int t = threadIdx.x;
    if (t == 0) { carry = 0; off[0] = 0; }
    __syncthreads();
    for (int base = 0; base < n; base += 1024) {
        int v = (base + t < n) ? deg[base + t] : 0;
        sh[t] = v;
        __syncthreads();
        for (int d = 1; d < 1024; d <<= 1) {
            int add = (t >= d) ? sh[t - d] : 0;
            __syncthreads();
            sh[t] += add;
            __syncthreads();
        }
        if (base + t < n) off[base + t + 1] = carry + sh[t];
        __syncthreads();
        if (t == 0) carry += sh[1023];
        __syncthreads();
    }
}

__global__ void k_scatter(const int* __restrict__ dst, const int* __restrict__ off,
                          int* __restrict__ cur, int* __restrict__ eid) {
    int e = blockIdx.x * blockDim.x + threadIdx.x;
    if (e >= EE) return;
    int d = dst[e];
    int p = atomicAdd(&cur[d], 1);
    eid[off[d] + p] = e;
}

// ---------------- BatchNorm ----------------
__global__ void k_bnstat(const float* __restrict__ x, float* __restrict__ s1,
                         float* __restrict__ s2, int F) {
    int c = blockIdx.x * blockDim.x + threadIdx.x;
    if (c >= F) return;
    int nchunks = gridDim.y;
    int chunk = (NN + nchunks - 1) / nchunks;
    int r0 = blockIdx.y * chunk;
    int r1 = r0 + chunk; if (r1 > NN) r1 = NN;
    float a = 0.f, b = 0.f;
    for (int r = r0; r < r1; r++) {
        float v = x[(size_t)r * F + c];
        a += v; b += v * v;
    }
    atomicAdd(&s1[c], a);
    atomicAdd(&s2[c], b);
}

__global__ void k_bnfin(const float* __restrict__ s1, const float* __restrict__ s2,
                        const float* __restrict__ g, const float* __restrict__ b,
                        float* __restrict__ scale, float* __restrict__ shift, int F) {
    int c = blockIdx.x * blockDim.x + threadIdx.x;
    if (c >= F) return;
    float invN = 1.f / (float)NN;
    float mu = s1[c] * invN;
    float var = s2[c] * invN - mu * mu;
    float rstd = rsqrtf(var + 1e-5f);
    float sc = rstd * g[c];
    scale[c] = sc;
    shift[c] = b[c] - mu * sc;
}

// ---------------- bf16-split prep ----------------
__global__ void k_prepA(const float* __restrict__ x, const float* __restrict__ scale,
                        const float* __restrict__ shift,
                        __nv_bfloat16* __restrict__ Ah, __nv_bfloat16* __restrict__ Al,
                        int F, int Kp) {
    size_t i = (size_t)blockIdx.x * blockDim.x + threadIdx.x;
    if (i >= (size_t)NN * Kp) return;
    int m = (int)(i / Kp), k = (int)(i % Kp);
    float v = 0.f;
    if (k < F) v = x[(size_t)m * F + k] * scale[k] + shift[k];
    __nv_bfloat16 h = __float2bfloat16(v);
    float lo = v - __bfloat162float(h);
    Ah[i] = h;
    Al[i] = __float2bfloat16(lo);
}

__global__ void k_prepB(const float* __restrict__ W,
                        __nv_bfloat16* __restrict__ Bh, __nv_bfloat16* __restrict__ Bl,
                        int K, int Kp) {
    size_t i = (size_t)blockIdx.x * blockDim.x + threadIdx.x;
    if (i >= (size_t)HIDD * Kp) return;
    int n = (int)(i / Kp), k = (int)(i % Kp);
    float v = (k < K) ? W[(size_t)k * HIDD + n] : 0.f;
    __nv_bfloat16 h = __float2bfloat16(v);
    float lo = v - __bfloat162float(h);
    Bh[i] = h;
    Bl[i] = __float2bfloat16(lo);
}

// ---------------- mma.sync helpers (base sm_103 ISA — no tcgen05) ----------------
__device__ __forceinline__ uint32_t smem_u32(const void* p) {
    uint32_t a;
    asm("{ .reg .u64 t; cvta.to.shared.u64 t, %1; cvt.u32.u64 %0, t; }" : "=r"(a) : "l"(p));
    return a;
}
__device__ __forceinline__ void sts128(uint32_t addr, uint4 v) {
    asm volatile("st.shared.v4.b32 [%0], {%1,%2,%3,%4};"
                 :: "r"(addr), "r"(v.x), "r"(v.y), "r"(v.z), "r"(v.w) : "memory");
}
__device__ __forceinline__ void cpasync16(uint32_t s, const void* g) {
    asm volatile("cp.async.ca.shared.global [%0], [%1], 16;" :: "r"(s), "l"(g));
}
#define CP_COMMIT() asm volatile("cp.async.commit_group;" ::: "memory")
#define CP_WAIT()   asm volatile("cp.async.wait_group 0;" ::: "memory")
#define SWZ(x) ((x) ^ (((x) >> 3) & 0x70))

#define LDSM4(r0, r1, r2, r3, addr) \
    asm volatile("ldmatrix.sync.aligned.m8n8.x4.shared.b16 {%0,%1,%2,%3}, [%4];" \
                 : "=r"(r0), "=r"(r1), "=r"(r2), "=r"(r3) : "r"(addr))

#define MMA_BF16(d, a0, a1, a2, a3, b0, b1) \
    asm volatile("mma.sync.aligned.m16n8k16.row.col.f32.bf16.bf16.f32 " \
                 "{%0,%1,%2,%3}, {%4,%5,%6,%7}, {%8,%9}, {%0,%1,%2,%3};" \
                 : "+f"((d)[0]), "+f"((d)[1]), "+f"((d)[2]), "+f"((d)[3]) \
                 : "r"(a0), "r"(a1), "r"(a2), "r"(a3), "r"(b0), "r"(b1))

// ---------------- split-bf16 GEMM via mma.sync ----------------
// grid.x = 16 n-tiles: 0-7 -> (B1 -> C1), 8-15 -> (B2 -> C2). C = A @ B^T.
// acc(fp32, registers) += Ah*Bh + Ah*Bl + Al*Bh
#define GT_SMEM (65536 + 1024)

__global__ __launch_bounds__(256, 2) void gemm_mma(
    const __nv_bfloat16* __restrict__ Ah, const __nv_bfloat16* __restrict__ Al, int Kp,
    const __nv_bfloat16* __restrict__ B1h, const __nv_bfloat16* __restrict__ B1l,
    const __nv_bfloat16* __restrict__ B2h, const __nv_bfloat16* __restrict__ B2l,
    float* __restrict__ C1, float* __restrict__ C2, int M)
{
    extern __shared__ char smraw[];
    uint32_t sb = (smem_u32(smraw) + 1023) & ~1023u;
    const uint32_t sAh = sb, sAl = sb + 16384, sBh = sb + 32768, sBl = sb + 49152;
    int tid = threadIdx.x, lane = tid & 31, wid = tid >> 5;
    int nt = blockIdx.x, mt = blockIdx.y;

    const __nv_bfloat16 *Bh, *Bl;
    float* C;
    int coloff;
    if (nt < 8) { Bh = B1h; Bl = B1l; C = C1; coloff = nt * 128; }
    else        { Bh = B2h; Bl = B2l; C = C2; coloff = (nt - 8) * 128; }

    int wm = wid & 1, wn = wid >> 1;   // 2 x 4 warp grid; warp tile 64x32

    float acc[4][4][4];
#pragma unroll
    for (int a = 0; a < 4; a++)
#pragma unroll
        for (int b = 0; b < 4; b++)
#pragma unroll
            for (int cc = 0; cc < 4; cc++) acc[a][b][cc] = 0.f;

    // chunk-invariant ldmatrix smem offsets
    uint32_t offA[4][4];  // [mi][k16]
    uint32_t offB[4][2];  // [k16][ntile-pair]
#pragma unroll
    for (int mi = 0; mi < 4; mi++) {
        int row = wm * 64 + mi * 16 + (lane & 15);
#pragma unroll
        for (int k16 = 0; k16 < 4; k16++)
            offA[mi][k16] = SWZ((uint32_t)(row * 128 + k16 * 32 + (lane >> 4) * 16));
    }
#pragma unroll
    for (int p = 0; p < 2; p++) {
        int row = wn * 32 + p * 16 + ((lane >> 4) << 3) + (lane & 7);
#pragma unroll
        for (int k16 = 0; k16 < 4; k16++)
            offB[k16][p] = SWZ((uint32_t)(row * 128 + k16 * 32 + (((lane >> 3) & 1) << 4)));
    }

    int q = tid & 7;        // 16B chunk within row
    int rr = tid >> 3;      // 0..31, rows rr + i*32

    int chunks = Kp >> 6;
    for (int c = 0; c < chunks; c++) {
        size_t kel = (size_t)c * 64 + q * 8;
#pragma unroll
        for (int i = 0; i < 4; i++) {
            int row = rr + i * 32;
            uint32_t soff = SWZ((uint32_t)(row * 128 + q * 16));
            int m = mt * 128 + row;
            if (m < M) {
                cpasync16(sAh + soff, Ah + (size_t)m * Kp + kel);
                cpasync16(sAl + soff, Al + (size_t)m * Kp + kel);
            } else {
                uint4 z = make_uint4(0, 0, 0, 0);
                sts128(sAh + soff, z);
                sts128(sAl + soff, z);
            }
            int nr = coloff + row;
            cpasync16(sBh + soff, Bh + (size_t)nr * Kp + kel);
            cpasync16(sBl + soff, Bl + (size_t)nr * Kp + kel);
        }
        CP_COMMIT();
        CP_WAIT();
        __syncthreads();

#pragma unroll
        for (int p = 0; p < 3; p++) {
            uint32_t ab = (p == 2) ? sAl : sAh;
            uint32_t bb = (p == 1) ? sBl : sBh;
#pragma unroll
            for (int k16 = 0; k16 < 4; k16++) {
                uint32_t b0[4], b1[4];
#pragma unroll
                for (int pp = 0; pp < 2; pp++) {
                    uint32_t r0_, r1_, r2_, r3_;
                    LDSM4(r0_, r1_, r2_, r3_, bb + offB[k16][pp]);
                    b0[pp * 2] = r0_; b1[pp * 2] = r1_;
                    b0[pp * 2 + 1] = r2_; b1[pp * 2 + 1] = r3_;
                }
#pragma unroll
                for (int mi = 0; mi < 4; mi++) {
                    uint32_t a0, a1, a2, a3;
                    LDSM4(a0, a1, a2, a3, ab + offA[mi][k16]);
#pragma unroll
                    for (int ni = 0; ni < 4; ni++)
                        MMA_BF16(acc[mi][ni], a0, a1, a2, a3, b0[ni], b1[ni]);
                }
            }
        }
        __syncthreads();
    }

    // epilogue: direct fp32 stores
#pragma unroll
    for (int mi = 0; mi < 4; mi++) {
        int gr = mt * 128 + wm * 64 + mi * 16 + (lane >> 2);
#pragma unroll
        for (int ni = 0; ni < 4; ni++) {
            int gc = coloff + wn * 32 + ni * 8 + ((lane & 3) << 1);
            if (gr < M)
                *(float2*)(C + (size_t)gr * HIDD + gc) = make_float2(acc[mi][ni][0], acc[mi][ni][1]);
            if (gr + 8 < M)
                *(float2*)(C + (size_t)(gr + 8) * HIDD + gc) = make_float2(acc[mi][ni][2], acc[mi][ni][3]);
        }
    }
}

// ---------------- layer-3 tiny GEMM (N=2 per matrix), from split-bf16 A ----------------
__global__ __launch_bounds__(128) void k_gemm_small(
    const __nv_bfloat16* __restrict__ Ah, const __nv_bfloat16* __restrict__ Al,
    const float* __restrict__ lw, const float* __restrict__ wg,
    float* __restrict__ lin, float* __restrict__ hg)
{
    int n = blockIdx.x, t = threadIdx.x;
    const __nv_bfloat16* ah = Ah + (size_t)n * HIDD;
    const __nv_bfloat16* al = Al + (size_t)n * HIDD;
    float a0 = 0, a1 = 0, a2 = 0, a3 = 0;
    for (int k = t; k < HIDD; k += 128) {
        float a = __bfloat162float(ah[k]) + __bfloat162float(al[k]);
        a0 += a * lw[k * 2];
        a1 += a * lw[k * 2 + 1];
        a2 += a * wg[k * 2];
        a3 += a * wg[k * 2 + 1];
    }
#pragma unroll
    for (int s = 16; s; s >>= 1) {
        a0 += __shfl_down_sync(0xFFFFFFFFu, a0, s);
        a1 += __shfl_down_sync(0xFFFFFFFFu, a1, s);
        a2 += __shfl_down_sync(0xFFFFFFFFu, a2, s);
        a3 += __shfl_down_sync(0xFFFFFFFFu, a3, s);
    }
    __shared__ float sm[4][4];
    if ((t & 31) == 0) {
        sm[t >> 5][0] = a0; sm[t >> 5][1] = a1; sm[t >> 5][2] = a2; sm[t >> 5][3] = a3;
    }
    __syncthreads();
    if (t == 0) {
        lin[(size_t)n * 2]     = sm[0][0] + sm[1][0] + sm[2][0] + sm[3][0];
        lin[(size_t)n * 2 + 1] = sm[0][1] + sm[1][1] + sm[2][1] + sm[3][1];
        hg [(size_t)n * 2]     = sm[0][2] + sm[1][2] + sm[2][2] + sm[3][2];
        hg [(size_t)n * 2 + 1] = sm[0][3] + sm[1][3] + sm[2][3] + sm[3][3];
    }
}

// ---------------- GAT pieces ----------------
__global__ void k_ve(const float* __restrict__ We, const float* __restrict__ attn,
                     float* __restrict__ ve, int H, int O) {
    int t = threadIdx.x;
    if (t >= H * EDK) return;
    int h = t / EDK, k = t % EDK;
    const float* a2 = attn + (size_t)(2 * H + h) * O;
    const float* w = We + (size_t)k * H * O + (size_t)h * O;
    float s = 0.f;
    for (int d = 0; d < O; d++) s += w[d] * a2[d];
    ve[k * H + h] = s;
}

__global__ void k_sdots(const float* __restrict__ hg, const float* __restrict__ attn,
                        float* __restrict__ ssrc, float* __restrict__ sdst, int H, int O) {
    int gw = (blockIdx.x * blockDim.x + threadIdx.x) >> 5;
    int lane = threadIdx.x & 31;
    if (gw >= NN * H) return;
    int n = gw / H, h = gw % H;
    const float* hr = hg + (size_t)n * H * O + (size_t)h * O;
    const float* a0 = attn + (size_t)h * O;
    const float* a1 = attn + (size_t)(H + h) * O;
    float d0 = 0.f, d1 = 0.f;
    for (int d = lane; d < O; d += 32) {
        float v = hr[d];
        d0 += v * a0[d];
        d1 += v * a1[d];
    }
#pragma unroll
    for (int s = 16; s; s >>= 1) {
        d0 += __shfl_down_sync(0xFFFFFFFFu, d0, s);
        d1 += __shfl_down_sync(0xFFFFFFFFu, d1, s);
    }
    if (lane == 0) { ssrc[gw] = d0; sdst[gw] = d1; }
}

__global__ void k_logits(const int* __restrict__ ei, const float* __restrict__ ea,
                         const float* __restrict__ ssrc, const float* __restrict__ sdst,
                         const float* __restrict__ ve, const float* __restrict__ at,
                         float* __restrict__ logw, int H) {
    int idx = blockIdx.x * blockDim.x + threadIdx.x;
    if (idx >= EE * H) return;
    int e = idx / H, h = idx % H;
    int s = ei[e], d = ei[EE + e];
    const float* row = ea + (size_t)e * EAC;
    float t = row[0];
    float se = 0.f;
#pragma unroll
    for (int k = 0; k < EDK; k++) se += row[1 + k] * ve[k * H + h];
    float l = ssrc[s * H + h] + sdst[d * H + h] + se + t * at[h];
    logw[idx] = (l > 0.f) ? l : 0.2f * l;
}

__global__ void k_softmax(const int* __restrict__ off, const int* __restrict__ eid,
                          float* __restrict__ logw, int H) {
    int idx = blockIdx.x * blockDim.x + threadIdx.x;
    if (idx >= NN * H) return;
    int n = idx / H, h = idx % H;
    int d0 = off[n], d1 = off[n + 1];
    if (d0 == d1) return;
    float m = -INFINITY;
    for (int i = d0; i < d1; i++) m = fmaxf(m, logw[eid[i] * H + h]);
    float s = 0.f;
    for (int i = d0; i < d1; i++) {
        float p = expf(logw[eid[i] * H + h] - m);
        logw[eid[i] * H + h] = p;
        s += p;
    }
    float inv = 1.f / (s + 1e-16f);
    for (int i = d0; i < d1; i++) logw[eid[i] * H + h] *= inv;
}

__global__ __launch_bounds__(256) void k_agg_big(
    const float* __restrict__ hg, const float* __restrict__ w,
    const int* __restrict__ off, const int* __restrict__ eid,
    const float* __restrict__ ea, const int* __restrict__ src,
    const float* __restrict__ We, const float* __restrict__ lin,
    const float* __restrict__ lb, const float* __restrict__ cb,
    float* __restrict__ out)
{
    int n = blockIdx.x;
    int t = threadIdx.x;
    __shared__ float qs[40];
    if (t < 40) qs[t] = 0.f;
    float acc0 = 0.f, acc1 = 0.f, acc2 = 0.f, acc3 = 0.f;
    int d0 = off[n], d1 = off[n + 1];
    for (int i = d0; i < d1; i++) {
        int e = eid[i];
        int s = src[e];
        float4 wv = *(const float4*)(w + (size_t)e * 4);
        const float* hr = hg + (size_t)s * 1024;
        acc0 += wv.x * hr[t];
        acc1 += wv.y * hr[t + 256];
        acc2 += wv.z * hr[t + 512];
        acc3 += wv.w * hr[t + 768];
        if (t < 40) {
            int h = t / 10, k = t % 10;
            float wh = (h == 0) ? wv.x : (h == 1) ? wv.y : (h == 2) ? wv.z : wv.w;
            qs[t] += wh * ea[(size_t)e * EAC + 1 + k];
        }
    }
    __syncthreads();
    float acch[4] = {acc0, acc1, acc2, acc3};
#pragma unroll
    for (int h = 0; h < 4; h++) {
        int f = h * 256 + t;
        float et = 0.f;
#pragma unroll
        for (int k = 0; k < 10; k++) et += qs[h * 10 + k] * We[k * 1024 + f];
        float v = lin[(size_t)n * 1024 + f] + lb[f] + cb[f] + acch[h] + et;
        out[(size_t)n * 1024 + f] = fmaxf(v, 0.f);
    }
}

__global__ void k_agg_small(
    const float* __restrict__ hg, const float* __restrict__ w,
    const int* __restrict__ off, const int* __restrict__ eid,
    const float* __restrict__ ea, const int* __restrict__ src,
    const float* __restrict__ We, const float* __restrict__ lin,
    const float* __restrict__ lb, const float* __restrict__ cb,
    float* __restrict__ out)
{
    int n = blockIdx.x * blockDim.x + threadIdx.x;
    if (n >= NN) return;
    float a0 = 0.f, a1 = 0.f;
    float q[10];
#pragma unroll
    for (int k = 0; k < 10; k++) q[k] = 0.f;
    int d0 = off[n], d1 = off[n + 1];
    for (int i = d0; i < d1; i++) {
        int e = eid[i];
        int s = src[e];
        float wv = w[e];
        a0 += wv * hg[(size_t)s * 2];
        a1 += wv * hg[(size_t)s * 2 + 1];
        const float* row = ea + (size_t)e * EAC;
#pragma unroll
        for (int k = 0; k < 10; k++) q[k] += wv * row[1 + k];
    }
    float e0 = 0.f, e1 = 0.f;
#pragma unroll
    for (int k = 0; k < 10; k++) { e0 += q[k] * We[k * 2]; e1 += q[k] * We[k * 2 + 1]; }
    float v0 = lin[(size_t)n * 2] + lb[0] + cb[0] + a0 + e0;
    float v1 = lin[(size_t)n * 2 + 1] + lb[1] + cb[1] + a1 + e1;
    out[(size_t)n * 2] = fmaxf(v0, 0.f);
    out[(size_t)n * 2 + 1] = fmaxf(v1, 0.f);
}

// ---------------- host driver ----------------
static inline int cdiv(int a, int b) { return (a + b - 1) / b; }

struct Scratch {
    float *lin, *hg, *h, *logw, *ssrc, *sdst, *s1, *s2, *scale, *shift, *ve;
    int *deg, *off, *cur, *eid;
    __nv_bfloat16 *Ah, *Al, *B1h, *B1l, *B2h, *B2l;
};

static void run_big_layer(const Scratch& S, const float* xin, int F, int Kp,
                          const float* Wg, const float* We, const float* attn,
                          const float* at, const float* cb,
                          const float* lw, const float* lb,
                          const float* g, const float* b,
                          float* out, const int* ei, const float* ea)
{
    const int H = 4, O = 256;
    k_zero_f<<<cdiv(F, 256), 256>>>(S.s1, F);
    k_zero_f<<<cdiv(F, 256), 256>>>(S.s2, F);
    k_bnstat<<<dim3(cdiv(F, 256), 40), 256>>>(xin, S.s1, S.s2, F);
    k_bnfin<<<cdiv(F, 256), 256>>>(S.s1, S.s2, g, b, S.scale, S.shift, F);
    size_t ta = (size_t)NN * Kp;
    k_prepA<<<(int)((ta + 255) / 256), 256>>>(xin, S.scale, S.shift, S.Ah, S.Al, F, Kp);
    size_t tb = (size_t)HIDD * Kp;
    k_prepB<<<(int)((tb + 255) / 256), 256>>>(lw, S.B1h, S.B1l, F, Kp);
    k_prepB<<<(int)((tb + 255) / 256), 256>>>(Wg, S.B2h, S.B2l, F, Kp);
    gemm_mma<<<dim3(16, cdiv(NN, 128)), 256, GT_SMEM>>>(
        S.Ah, S.Al, Kp, S.B1h, S.B1l, S.B2h, S.B2l, S.lin, S.hg, NN);
    k_ve<<<1, 64>>>(We, attn, S.ve, H, O);
    k_sdots<<<cdiv(NN * H * 32, 256), 256>>>(S.hg, attn, S.ssrc, S.sdst, H, O);
    k_logits<<<cdiv(EE * H, 256), 256>>>(ei, ea, S.ssrc, S.sdst, S.ve, at, S.logw, H);
    k_softmax<<<cdiv(NN * H, 256), 256>>>(S.off, S.eid, S.logw, H);
    k_agg_big<<<NN, 256>>>(S.hg, S.logw, S.off, S.eid, ea, ei, We, S.lin, lb, cb, out);
}

extern "C" void kernel_launch(void* const* d_in, const int* in_sizes, int n_in,
                              void* d_out, int out_size)
{
    const float* x  = (const float*)d_in[0];
    const int*   ei = (const int*)d_in[1];
    const float* ea = (const float*)d_in[2];

    const float *Wg[3], *We[3], *attn[3], *at[3], *cb[3];
    const float *lw[3], *lb[3], *gg[3], *bb[3];

    if (in_sizes[8] == 1048576) {
        for (int i = 0; i < 3; i++) {
            Wg[i]   = (const float*)d_in[3 + 5 * i];
            We[i]   = (const float*)d_in[4 + 5 * i];
            attn[i] = (const float*)d_in[5 + 5 * i];
            at[i]   = (const float*)d_in[6 + 5 * i];
            cb[i]   = (const float*)d_in[7 + 5 * i];
            lw[i]   = (const float*)d_in[18 + 4 * i];
            lb[i]   = (const float*)d_in[19 + 4 * i];
            gg[i]   = (const float*)d_in[20 + 4 * i];
            bb[i]   = (const float*)d_in[21 + 4 * i];
        }
    } else {
        for (int i = 0; i < 3; i++) {
            Wg[i]   = (const float*)d_in[3 + 9 * i];
            We[i]   = (const float*)d_in[4 + 9 * i];
            attn[i] = (const float*)d_in[5 + 9 * i];
            at[i]   = (const float*)d_in[6 + 9 * i];
            cb[i]   = (const float*)d_in[7 + 9 * i];
            lw[i]   = (const float*)d_in[8 + 9 * i];
            lb[i]   = (const float*)d_in[9 + 9 * i];
            gg[i]   = (const float*)d_in[10 + 9 * i];
            bb[i]   = (const float*)d_in[11 + 9 * i];
        }
    }

    Scratch S;
    cudaGetSymbolAddress((void**)&S.lin, g_lin);
    cudaGetSymbolAddress((void**)&S.hg, g_hg);
    cudaGetSymbolAddress((void**)&S.h, g_h);
    cudaGetSymbolAddress((void**)&S.logw, g_logw);
    cudaGetSymbolAddress((void**)&S.ssrc, g_ssrc);
    cudaGetSymbolAddress((void**)&S.sdst, g_sdst);
    cudaGetSymbolAddress((void**)&S.s1, g_s1);
    cudaGetSymbolAddress((void**)&S.s2, g_s2);
    cudaGetSymbolAddress((void**)&S.scale, g_scale);
    cudaGetSymbolAddress((void**)&S.shift, g_shift);
    cudaGetSymbolAddress((void**)&S.ve, g_ve);
    cudaGetSymbolAddress((void**)&S.deg, g_deg);
    cudaGetSymbolAddress((void**)&S.off, g_off);
    cudaGetSymbolAddress((void**)&S.cur, g_cur);
    cudaGetSymbolAddress((void**)&S.eid, g_eid);
    cudaGetSymbolAddress((void**)&S.Ah, g_Ah);
    cudaGetSymbolAddress((void**)&S.Al, g_Al);
    cudaGetSymbolAddress((void**)&S.B1h, g_B1h);
    cudaGetSymbolAddress((void**)&S.B1l, g_B1l);
    cudaGetSymbolAddress((void**)&S.B2h, g_B2h);
    cudaGetSymbolAddress((void**)&S.B2l, g_B2l);

    cudaFuncSetAttribute(gemm_mma, cudaFuncAttributeMaxDynamicSharedMemorySize, GT_SMEM);

    // ---- CSR by destination ----
    k_zero_i<<<cdiv(NN, 256), 256>>>(S.deg, NN);
    k_hist<<<cdiv(EE, 256), 256>>>(ei + EE, S.deg);
    k_scan<<<1, 1024>>>(S.deg, S.off, NN);
    k_zero_i<<<cdiv(NN, 256), 256>>>(S.cur, NN);
    k_scatter<<<cdiv(EE, 256), 256>>>(ei + EE, S.off, S.cur, S.eid);

    // ---- layers 1 & 2 (H=4, O=256) via mma.sync GEMM ----
    run_big_layer(S, x,   F1,   192,  Wg[0], We[0], attn[0], at[0], cb[0], lw[0], lb[0], gg[0], bb[0], S.h, ei, ea);
    run_big_layer(S, S.h, HIDD, 1024, Wg[1], We[1], attn[1], at[1], cb[1], lw[1], lb[1], gg[1], bb[1], S.h, ei, ea);

    // ---- layer 3 (H=1, O=2) ----
    k_zero_f<<<cdiv(HIDD, 256), 256>>>(S.s1, HIDD);
    k_zero_f<<<cdiv(HIDD, 256), 256>>>(S.s2, HIDD);
    k_bnstat<<<dim3(cdiv(HIDD, 256), 40), 256>>>(S.h, S.s1, S.s2, HIDD);
    k_bnfin<<<cdiv(HIDD, 256), 256>>>(S.s1, S.s2, gg[2], bb[2], S.scale, S.shift, HIDD);
    size_t ta = (size_t)NN * HIDD;
    k_prepA<<<(int)((ta + 255) / 256), 256>>>(S.h, S.scale, S.shift, S.Ah, S.Al, HIDD, HIDD);
    k_gemm_small<<<NN, 128>>>(S.Ah, S.Al, lw[2], Wg[2], S.lin, S.hg);
    k_ve<<<1, 64>>>(We[2], attn[2], S.ve, 1, 2);
    k_sdots<<<cdiv(NN * 1 * 32, 256), 256>>>(S.hg, attn[2], S.ssrc, S.sdst, 1, 2);
    k_logits<<<cdiv(EE * 1, 256), 256>>>(ei, ea, S.ssrc, S.sdst, S.ve, at[2], S.logw, 1);
    k_softmax<<<cdiv(NN * 1, 256), 256>>>(S.off, S.eid, S.logw, 1);
    k_agg_small<<<cdiv(NN, 256), 256>>>(S.hg, S.logw, S.off, S.eid, ea, ei, We[2], S.lin, lb[2], cb[2], (float*)d_out);
}

// round 6
// speedup vs baseline: 2.8625x; 1.3203x over previous
#include <cuda_runtime.h>
#include <cuda_bf16.h>
#include <cstdint>
#include <math.h>

#define NN   20000
#define EE   100000
#define F1   167
#define HIDD 1024
#define EDK  10
#define EAC  12

// ---------------- scratch (device globals) ----------------
__device__ float g_lin[(size_t)NN * HIDD];
__device__ float g_hg [(size_t)NN * HIDD];
__device__ float g_h  [(size_t)NN * HIDD];
__device__ float g_logw[(size_t)EE * 4];
__device__ float g_ssrc[(size_t)NN * 4];
__device__ float g_sdst[(size_t)NN * 4];
__device__ float g_s1[HIDD];
__device__ float g_s2[HIDD];
__device__ float g_scale[HIDD];
__device__ float g_shift[HIDD];
__device__ float g_ve[EDK * 4];
__device__ int   g_deg[NN];
__device__ int   g_off[NN + 1];
__device__ int   g_cur[NN];
__device__ int   g_eid[EE];
__device__ __nv_bfloat16 g_Ah[(size_t)NN * HIDD];
__device__ __nv_bfloat16 g_Al[(size_t)NN * HIDD];
__device__ __nv_bfloat16 g_B1h[(size_t)HIDD * HIDD];
__device__ __nv_bfloat16 g_B1l[(size_t)HIDD * HIDD];
__device__ __nv_bfloat16 g_B2h[(size_t)HIDD * HIDD];
__device__ __nv_bfloat16 g_B2l[(size_t)HIDD * HIDD];

// ---------------- utility ----------------
__global__ void k_zero_f(float* p, int n) {
    int i = blockIdx.x * blockDim.x + threadIdx.x;
    if (i < n) p[i] = 0.f;
}
__global__ void k_zero_i(int* p, int n) {
    int i = blockIdx.x * blockDim.x + threadIdx.x;
    if (i < n) p[i] = 0;
}

// ---------------- CSR build ----------------
__global__ void k_hist(const int* __restrict__ dst, int* __restrict__ deg) {
    int e = blockIdx.x * blockDim.x + threadIdx.x;
    if (e < EE) atomicAdd(&deg[dst[e]], 1);
}

__global__ void k_scan(const int* __restrict__ deg, int* __restrict__ off, int n) {
    __shared__ int sh[1024];
    __shared__ int carry;
    int t = threadIdx.x;
    if (t == 0) { carry = 0; off[0] = 0; }
    __syncthreads();
    for (int base = 0; base < n; base += 1024) {
        int v = (base + t < n) ? deg[base + t] : 0;
        sh[t] = v;
        __syncthreads();
        for (int d = 1; d < 1024; d <<= 1) {
            int add = (t >= d) ? sh[t - d] : 0;
            __syncthreads();
            sh[t] += add;
            __syncthreads();
        }
        if (base + t < n) off[base + t + 1] = carry + sh[t];
        __syncthreads();
        if (t == 0) carry += sh[1023];
        __syncthreads();
    }
}

__global__ void k_scatter(const int* __restrict__ dst, const int* __restrict__ off,
                          int* __restrict__ cur, int* __restrict__ eid) {
    int e = blockIdx.x * blockDim.x + threadIdx.x;
    if (e >= EE) return;
    int d = dst[e];
    int p = atomicAdd(&cur[d], 1);
    eid[off[d] + p] = e;
}

// ---------------- BatchNorm ----------------
__global__ void k_bnstat(const float* __restrict__ x, float* __restrict__ s1,
                         float* __restrict__ s2, int F) {
    int c = blockIdx.x * blockDim.x + threadIdx.x;
    if (c >= F) return;
    int nchunks = gridDim.y;
    int chunk = (NN + nchunks - 1) / nchunks;
    int r0 = blockIdx.y * chunk;
    int r1 = r0 + chunk; if (r1 > NN) r1 = NN;
    float a = 0.f, b = 0.f;
    for (int r = r0; r < r1; r++) {
        float v = x[(size_t)r * F + c];
        a += v; b += v * v;
    }
    atomicAdd(&s1[c], a);
    atomicAdd(&s2[c], b);
}

__global__ void k_bnfin(const float* __restrict__ s1, const float* __restrict__ s2,
                        const float* __restrict__ g, const float* __restrict__ b,
                        float* __restrict__ scale, float* __restrict__ shift, int F) {
    int c = blockIdx.x * blockDim.x + threadIdx.x;
    if (c >= F) return;
    float invN = 1.f / (float)NN;
    float mu = s1[c] * invN;
    float var = s2[c] * invN - mu * mu;
    float rstd = rsqrtf(var + 1e-5f);
    float sc = rstd * g[c];
    scale[c] = sc;
    shift[c] = b[c] - mu * sc;
}

// ---------------- bf16-split prep ----------------
__global__ void k_prepA(const float* __restrict__ x, const float* __restrict__ scale,
                        const float* __restrict__ shift,
                        __nv_bfloat16* __restrict__ Ah, __nv_bfloat16* __restrict__ Al,
                        int F, int Kp) {
    size_t i = (size_t)blockIdx.x * blockDim.x + threadIdx.x;
    if (i >= (size_t)NN * Kp) return;
    int m = (int)(i / Kp), k = (int)(i % Kp);
    float v = 0.f;
    if (k < F) v = x[(size_t)m * F + k] * scale[k] + shift[k];
    __nv_bfloat16 h = __float2bfloat16(v);
    float lo = v - __bfloat162float(h);
    Ah[i] = h;
    Al[i] = __float2bfloat16(lo);
}

__global__ void k_prepB(const float* __restrict__ W,
                        __nv_bfloat16* __restrict__ Bh, __nv_bfloat16* __restrict__ Bl,
                        int K, int Kp) {
    size_t i = (size_t)blockIdx.x * blockDim.x + threadIdx.x;
    if (i >= (size_t)HIDD * Kp) return;
    int n = (int)(i / Kp), k = (int)(i % Kp);
    float v = (k < K) ? W[(size_t)k * HIDD + n] : 0.f;
    __nv_bfloat16 h = __float2bfloat16(v);
    float lo = v - __bfloat162float(h);
    Bh[i] = h;
    Bl[i] = __float2bfloat16(lo);
}

// ---------------- mma.sync helpers ----------------
__device__ __forceinline__ uint32_t smem_u32(const void* p) {
    uint32_t a;
    asm("{ .reg .u64 t; cvta.to.shared.u64 t, %1; cvt.u32.u64 %0, t; }" : "=r"(a) : "l"(p));
    return a;
}
__device__ __forceinline__ void sts128(uint32_t addr, uint4 v) {
    asm volatile("st.shared.v4.b32 [%0], {%1,%2,%3,%4};"
                 :: "r"(addr), "r"(v.x), "r"(v.y), "r"(v.z), "r"(v.w) : "memory");
}
__device__ __forceinline__ void cpasync16(uint32_t s, const void* g) {
    asm volatile("cp.async.cg.shared.global [%0], [%1], 16;" :: "r"(s), "l"(g));
}
#define CP_COMMIT() asm volatile("cp.async.commit_group;" ::: "memory")
#define CP_WAIT0()  asm volatile("cp.async.wait_group 0;" ::: "memory")
#define CP_WAIT1()  asm volatile("cp.async.wait_group 1;" ::: "memory")
#define SWZ(x) ((x) ^ (((x) >> 3) & 0x70))

#define LDSM4(r0, r1, r2, r3, addr) \
    asm volatile("ldmatrix.sync.aligned.m8n8.x4.shared.b16 {%0,%1,%2,%3}, [%4];" \
                 : "=r"(r0), "=r"(r1), "=r"(r2), "=r"(r3) : "r"(addr))

#define MMA_BF16(d, a0, a1, a2, a3, b0, b1) \
    asm volatile("mma.sync.aligned.m16n8k16.row.col.f32.bf16.bf16.f32 " \
                 "{%0,%1,%2,%3}, {%4,%5,%6,%7}, {%8,%9}, {%0,%1,%2,%3};" \
                 : "+f"((d)[0]), "+f"((d)[1]), "+f"((d)[2]), "+f"((d)[3]) \
                 : "r"(a0), "r"(a1), "r"(a2), "r"(a3), "r"(b0), "r"(b1))

// ---------------- split-bf16 GEMM via mma.sync, 2-stage cp.async pipeline ----------------
// grid.x = 16 n-tiles: 0-7 -> (B1 -> C1), 8-15 -> (B2 -> C2). C = A @ B^T.
// acc(fp32, regs) += Ah*Bh + Ah*Bl + Al*Bh
#define STAGE_BYTES 65536
#define GT_SMEM (2 * STAGE_BYTES + 1024)

__global__ __launch_bounds__(256, 1) void gemm_mma(
    const __nv_bfloat16* __restrict__ Ah, const __nv_bfloat16* __restrict__ Al, int Kp,
    const __nv_bfloat16* __restrict__ B1h, const __nv_bfloat16* __restrict__ B1l,
    const __nv_bfloat16* __restrict__ B2h, const __nv_bfloat16* __restrict__ B2l,
    float* __restrict__ C1, float* __restrict__ C2, int M)
{
    extern __shared__ char smraw[];
    uint32_t sb = (smem_u32(smraw) + 1023) & ~1023u;
    int tid = threadIdx.x, lane = tid & 31, wid = tid >> 5;
    int nt = blockIdx.x, mt = blockIdx.y;

    const __nv_bfloat16 *Bh, *Bl;
    float* C;
    int coloff;
    if (nt < 8) { Bh = B1h; Bl = B1l; C = C1; coloff = nt * 128; }
    else        { Bh = B2h; Bl = B2l; C = C2; coloff = (nt - 8) * 128; }

    int wm = wid & 1, wn = wid >> 1;   // 2 x 4 warp grid; warp tile 64x32

    float acc[4][4][4];
#pragma unroll
    for (int a = 0; a < 4; a++)
#pragma unroll
        for (int b = 0; b < 4; b++)
#pragma unroll
            for (int cc = 0; cc < 4; cc++) acc[a][b][cc] = 0.f;

    // chunk-invariant ldmatrix offsets (relative to stage base; tile offsets added below)
    uint32_t offA[4][4];  // [mi][k16]
    uint32_t offB[4][2];  // [k16][pair]
#pragma unroll
    for (int mi = 0; mi < 4; mi++) {
        int row = wm * 64 + mi * 16 + (lane & 15);
#pragma unroll
        for (int k16 = 0; k16 < 4; k16++)
            offA[mi][k16] = SWZ((uint32_t)(row * 128 + k16 * 32 + (lane >> 4) * 16));
    }
#pragma unroll
    for (int p = 0; p < 2; p++) {
        int row = wn * 32 + p * 16 + ((lane >> 4) << 3) + (lane & 7);
#pragma unroll
        for (int k16 = 0; k16 < 4; k16++)
            offB[k16][p] = SWZ((uint32_t)(row * 128 + k16 * 32 + (((lane >> 3) & 1) << 4)));
    }

    int q = tid & 7;        // 16B chunk within 128B row
    int rr = tid >> 3;      // 0..31 -> rows rr + i*32
    int chunks = Kp >> 6;

    auto load_stage = [&](int c, uint32_t base) {
        uint32_t bAh = base, bAl = base + 16384, bBh = base + 32768, bBl = base + 49152;
        size_t kel = (size_t)c * 64 + q * 8;
#pragma unroll
        for (int i = 0; i < 4; i++) {
            int row = rr + i * 32;
            uint32_t soff = SWZ((uint32_t)(row * 128 + q * 16));
            int m = mt * 128 + row;
            if (m < M) {
                cpasync16(bAh + soff, Ah + (size_t)m * Kp + kel);
                cpasync16(bAl + soff, Al + (size_t)m * Kp + kel);
            } else {
                uint4 z = make_uint4(0, 0, 0, 0);
                sts128(bAh + soff, z);
                sts128(bAl + soff, z);
            }
            int nr = coloff + row;
            cpasync16(bBh + soff, Bh + (size_t)nr * Kp + kel);
            cpasync16(bBl + soff, Bl + (size_t)nr * Kp + kel);
        }
        CP_COMMIT();
    };

    load_stage(0, sb);

    for (int c = 0; c < chunks; c++) {
        uint32_t cur = sb + (uint32_t)(c & 1) * STAGE_BYTES;
        if (c + 1 < chunks) {
            load_stage(c + 1, sb + (uint32_t)((c + 1) & 1) * STAGE_BYTES);
            CP_WAIT1();
        } else {
            CP_WAIT0();
        }
        __syncthreads();

        uint32_t cAh = cur, cAl = cur + 16384, cBh = cur + 32768, cBl = cur + 49152;
#pragma unroll
        for (int k16 = 0; k16 < 4; k16++) {
            // load all fragments for this k16 once
            uint32_t ah0[4], ah1[4], ah2[4], ah3[4];
            uint32_t al0[4], al1[4], al2[4], al3[4];
#pragma unroll
            for (int mi = 0; mi < 4; mi++) {
                LDSM4(ah0[mi], ah1[mi], ah2[mi], ah3[mi], cAh + offA[mi][k16]);
                LDSM4(al0[mi], al1[mi], al2[mi], al3[mi], cAl + offA[mi][k16]);
            }
            uint32_t bh0[4], bh1[4], bl0[4], bl1[4];
#pragma unroll
            for (int pp = 0; pp < 2; pp++) {
                uint32_t r0_, r1_, r2_, r3_;
                LDSM4(r0_, r1_, r2_, r3_, cBh + offB[k16][pp]);
                bh0[pp * 2] = r0_; bh1[pp * 2] = r1_;
                bh0[pp * 2 + 1] = r2_; bh1[pp * 2 + 1] = r3_;
                LDSM4(r0_, r1_, r2_, r3_, cBl + offB[k16][pp]);
                bl0[pp * 2] = r0_; bl1[pp * 2] = r1_;
                bl0[pp * 2 + 1] = r2_; bl1[pp * 2 + 1] = r3_;
            }
            // 3 correction passes from registers
#pragma unroll
            for (int mi = 0; mi < 4; mi++) {
#pragma unroll
                for (int ni = 0; ni < 4; ni++) {
                    MMA_BF16(acc[mi][ni], ah0[mi], ah1[mi], ah2[mi], ah3[mi], bh0[ni], bh1[ni]);
                    MMA_BF16(acc[mi][ni], ah0[mi], ah1[mi], ah2[mi], ah3[mi], bl0[ni], bl1[ni]);
                    MMA_BF16(acc[mi][ni], al0[mi], al1[mi], al2[mi], al3[mi], bh0[ni], bh1[ni]);
                }
            }
        }
        __syncthreads();
    }

    // epilogue
#pragma unroll
    for (int mi = 0; mi < 4; mi++) {
        int gr = mt * 128 + wm * 64 + mi * 16 + (lane >> 2);
#pragma unroll
        for (int ni = 0; ni < 4; ni++) {
            int gc = coloff + wn * 32 + ni * 8 + ((lane & 3) << 1);
            if (gr < M)
                *(float2*)(C + (size_t)gr * HIDD + gc) = make_float2(acc[mi][ni][0], acc[mi][ni][1]);
            if (gr + 8 < M)
                *(float2*)(C + (size_t)(gr + 8) * HIDD + gc) = make_float2(acc[mi][ni][2], acc[mi][ni][3]);
        }
    }
}

// ---------------- layer-3 tiny GEMM ----------------
__global__ __launch_bounds__(128) void k_gemm_small(
    const __nv_bfloat16* __restrict__ Ah, const __nv_bfloat16* __restrict__ Al,
    const float* __restrict__ lw, const float* __restrict__ wg,
    float* __restrict__ lin, float* __restrict__ hg)
{
    int n = blockIdx.x, t = threadIdx.x;
    const __nv_bfloat16* ah = Ah + (size_t)n * HIDD;
    const __nv_bfloat16* al = Al + (size_t)n * HIDD;
    float a0 = 0, a1 = 0, a2 = 0, a3 = 0;
    for (int k = t; k < HIDD; k += 128) {
        float a = __bfloat162float(ah[k]) + __bfloat162float(al[k]);
        a0 += a * lw[k * 2];
        a1 += a * lw[k * 2 + 1];
        a2 += a * wg[k * 2];
        a3 += a * wg[k * 2 + 1];
    }
#pragma unroll
    for (int s = 16; s; s >>= 1) {
        a0 += __shfl_down_sync(0xFFFFFFFFu, a0, s);
        a1 += __shfl_down_sync(0xFFFFFFFFu, a1, s);
        a2 += __shfl_down_sync(0xFFFFFFFFu, a2, s);
        a3 += __shfl_down_sync(0xFFFFFFFFu, a3, s);
    }
    __shared__ float sm[4][4];
    if ((t & 31) == 0) {
        sm[t >> 5][0] = a0; sm[t >> 5][1] = a1; sm[t >> 5][2] = a2; sm[t >> 5][3] = a3;
    }
    __syncthreads();
    if (t == 0) {
        lin[(size_t)n * 2]     = sm[0][0] + sm[1][0] + sm[2][0] + sm[3][0];
        lin[(size_t)n * 2 + 1] = sm[0][1] + sm[1][1] + sm[2][1] + sm[3][1];
        hg [(size_t)n * 2]     = sm[0][2] + sm[1][2] + sm[2][2] + sm[3][2];
        hg [(size_t)n * 2 + 1] = sm[0][3] + sm[1][3] + sm[2][3] + sm[3][3];
    }
}

// ---------------- GAT pieces ----------------
__global__ void k_ve(const float* __restrict__ We, const float* __restrict__ attn,
                     float* __restrict__ ve, int H, int O) {
    int t = threadIdx.x;
    if (t >= H * EDK) return;
    int h = t / EDK, k = t % EDK;
    const float* a2 = attn + (size_t)(2 * H + h) * O;
    const float* w = We + (size_t)k * H * O + (size_t)h * O;
    float s = 0.f;
    for (int d = 0; d < O; d++) s += w[d] * a2[d];
    ve[k * H + h] = s;
}

__global__ void k_sdots(const float* __restrict__ hg, const float* __restrict__ attn,
                        float* __restrict__ ssrc, float* __restrict__ sdst, int H, int O) {
    int gw = (blockIdx.x * blockDim.x + threadIdx.x) >> 5;
    int lane = threadIdx.x & 31;
    if (gw >= NN * H) return;
    int n = gw / H, h = gw % H;
    const float* hr = hg + (size_t)n * H * O + (size_t)h * O;
    const float* a0 = attn + (size_t)h * O;
    const float* a1 = attn + (size_t)(H + h) * O;
    float d0 = 0.f, d1 = 0.f;
    for (int d = lane; d < O; d += 32) {
        float v = hr[d];
        d0 += v * a0[d];
        d1 += v * a1[d];
    }
#pragma unroll
    for (int s = 16; s; s >>= 1) {
        d0 += __shfl_down_sync(0xFFFFFFFFu, d0, s);
        d1 += __shfl_down_sync(0xFFFFFFFFu, d1, s);
    }
    if (lane == 0) { ssrc[gw] = d0; sdst[gw] = d1; }
}

__global__ void k_logits(const int* __restrict__ ei, const float* __restrict__ ea,
                         const float* __restrict__ ssrc, const float* __restrict__ sdst,
                         const float* __restrict__ ve, const float* __restrict__ at,
                         float* __restrict__ logw, int H) {
    int idx = blockIdx.x * blockDim.x + threadIdx.x;
    if (idx >= EE * H) return;
    int e = idx / H, h = idx % H;
    int s = ei[e], d = ei[EE + e];
    const float* row = ea + (size_t)e * EAC;
    float t = row[0];
    float se = 0.f;
#pragma unroll
    for (int k = 0; k < EDK; k++) se += row[1 + k] * ve[k * H + h];
    float l = ssrc[s * H + h] + sdst[d * H + h] + se + t * at[h];
    logw[idx] = (l > 0.f) ? l : 0.2f * l;
}

__global__ void k_softmax(const int* __restrict__ off, const int* __restrict__ eid,
                          float* __restrict__ logw, int H) {
    int idx = blockIdx.x * blockDim.x + threadIdx.x;
    if (idx >= NN * H) return;
    int n = idx / H, h = idx % H;
    int d0 = off[n], d1 = off[n + 1];
    if (d0 == d1) return;
    float m = -INFINITY;
    for (int i = d0; i < d1; i++) m = fmaxf(m, logw[eid[i] * H + h]);
    float s = 0.f;
    for (int i = d0; i < d1; i++) {
        float p = expf(logw[eid[i] * H + h] - m);
        logw[eid[i] * H + h] = p;
        s += p;
    }
    float inv = 1.f / (s + 1e-16f);
    for (int i = d0; i < d1; i++) logw[eid[i] * H + h] *= inv;
}

__global__ __launch_bounds__(256) void k_agg_big(
    const float* __restrict__ hg, const float* __restrict__ w,
    const int* __restrict__ off, const int* __restrict__ eid,
    const float* __restrict__ ea, const int* __restrict__ src,
    const float* __restrict__ We, const float* __restrict__ lin,
    const float* __restrict__ lb, const float* __restrict__ cb,
    float* __restrict__ out)
{
    int n = blockIdx.x;
    int t = threadIdx.x;
    __shared__ float qs[40];
    if (t < 40) qs[t] = 0.f;
    float acc0 = 0.f, acc1 = 0.f, acc2 = 0.f, acc3 = 0.f;
    int d0 = off[n], d1 = off[n + 1];
    for (int i = d0; i < d1; i++) {
        int e = eid[i];
        int s = src[e];
        float4 wv = *(const float4*)(w + (size_t)e * 4);
        const float* hr = hg + (size_t)s * 1024;
        acc0 += wv.x * hr[t];
        acc1 += wv.y * hr[t + 256];
        acc2 += wv.z * hr[t + 512];
        acc3 += wv.w * hr[t + 768];
        if (t < 40) {
            int h = t / 10, k = t % 10;
            float wh = (h == 0) ? wv.x : (h == 1) ? wv.y : (h == 2) ? wv.z : wv.w;
            qs[t] += wh * ea[(size_t)e * EAC + 1 + k];
        }
    }
    __syncthreads();
    float acch[4] = {acc0, acc1, acc2, acc3};
#pragma unroll
    for (int h = 0; h < 4; h++) {
        int f = h * 256 + t;
        float et = 0.f;
#pragma unroll
        for (int k = 0; k < 10; k++) et += qs[h * 10 + k] * We[k * 1024 + f];
        float v = lin[(size_t)n * 1024 + f] + lb[f] + cb[f] + acch[h] + et;
        out[(size_t)n * 1024 + f] = fmaxf(v, 0.f);
    }
}

__global__ void k_agg_small(
    const float* __restrict__ hg, const float* __restrict__ w,
    const int* __restrict__ off, const int* __restrict__ eid,
    const float* __restrict__ ea, const int* __restrict__ src,
    const float* __restrict__ We, const float* __restrict__ lin,
    const float* __restrict__ lb, const float* __restrict__ cb,
    float* __restrict__ out)
{
    int n = blockIdx.x * blockDim.x + threadIdx.x;
    if (n >= NN) return;
    float a0 = 0.f, a1 = 0.f;
    float q[10];
#pragma unroll
    for (int k = 0; k < 10; k++) q[k] = 0.f;
    int d0 = off[n], d1 = off[n + 1];
    for (int i = d0; i < d1; i++) {
        int e = eid[i];
        int s = src[e];
        float wv = w[e];
        a0 += wv * hg[(size_t)s * 2];
        a1 += wv * hg[(size_t)s * 2 + 1];
        const float* row = ea + (size_t)e * EAC;
#pragma unroll
        for (int k = 0; k < 10; k++) q[k] += wv * row[1 + k];
    }
    float e0 = 0.f, e1 = 0.f;
#pragma unroll
    for (int k = 0; k < 10; k++) { e0 += q[k] * We[k * 2]; e1 += q[k] * We[k * 2 + 1]; }
    float v0 = lin[(size_t)n * 2] + lb[0] + cb[0] + a0 + e0;
    float v1 = lin[(size_t)n * 2 + 1] + lb[1] + cb[1] + a1 + e1;
    out[(size_t)n * 2] = fmaxf(v0, 0.f);
    out[(size_t)n * 2 + 1] = fmaxf(v1, 0.f);
}

// ---------------- host driver ----------------
static inline int cdiv(int a, int b) { return (a + b - 1) / b; }

struct Scratch {
    float *lin, *hg, *h, *logw, *ssrc, *sdst, *s1, *s2, *scale, *shift, *ve;
    int *deg, *off, *cur, *eid;
    __nv_bfloat16 *Ah, *Al, *B1h, *B1l, *B2h, *B2l;
};

static void run_big_layer(const Scratch& S, const float* xin, int F, int Kp,
                          const float* Wg, const float* We, const float* attn,
                          const float* at, const float* cb,
                          const float* lw, const float* lb,
                          const float* g, const float* b,
                          float* out, const int* ei, const float* ea)
{
    const int H = 4, O = 256;
    k_zero_f<<<cdiv(F, 256), 256>>>(S.s1, F);
    k_zero_f<<<cdiv(F, 256), 256>>>(S.s2, F);
    k_bnstat<<<dim3(cdiv(F, 256), 40), 256>>>(xin, S.s1, S.s2, F);
    k_bnfin<<<cdiv(F, 256), 256>>>(S.s1, S.s2, g, b, S.scale, S.shift, F);
    size_t ta = (size_t)NN * Kp;
    k_prepA<<<(int)((ta + 255) / 256), 256>>>(xin, S.scale, S.shift, S.Ah, S.Al, F, Kp);
    size_t tb = (size_t)HIDD * Kp;
    k_prepB<<<(int)((tb + 255) / 256), 256>>>(lw, S.B1h, S.B1l, F, Kp);
    k_prepB<<<(int)((tb + 255) / 256), 256>>>(Wg, S.B2h, S.B2l, F, Kp);
    gemm_mma<<<dim3(16, cdiv(NN, 128)), 256, GT_SMEM>>>(
        S.Ah, S.Al, Kp, S.B1h, S.B1l, S.B2h, S.B2l, S.lin, S.hg, NN);
    k_ve<<<1, 64>>>(We, attn, S.ve, H, O);
    k_sdots<<<cdiv(NN * H * 32, 256), 256>>>(S.hg, attn, S.ssrc, S.sdst, H, O);
    k_logits<<<cdiv(EE * H, 256), 256>>>(ei, ea, S.ssrc, S.sdst, S.ve, at, S.logw, H);
    k_softmax<<<cdiv(NN * H, 256), 256>>>(S.off, S.eid, S.logw, H);
    k_agg_big<<<NN, 256>>>(S.hg, S.logw, S.off, S.eid, ea, ei, We, S.lin, lb, cb, out);
}

extern "C" void kernel_launch(void* const* d_in, const int* in_sizes, int n_in,
                              void* d_out, int out_size)
{
    const float* x  = (const float*)d_in[0];
    const int*   ei = (const int*)d_in[1];
    const float* ea = (const float*)d_in[2];

    const float *Wg[3], *We[3], *attn[3], *at[3], *cb[3];
    const float *lw[3], *lb[3], *gg[3], *bb[3];

    if (in_sizes[8] == 1048576) {
        for (int i = 0; i < 3; i++) {
            Wg[i]   = (const float*)d_in[3 + 5 * i];
            We[i]   = (const float*)d_in[4 + 5 * i];
            attn[i] = (const float*)d_in[5 + 5 * i];
            at[i]   = (const float*)d_in[6 + 5 * i];
            cb[i]   = (const float*)d_in[7 + 5 * i];
            lw[i]   = (const float*)d_in[18 + 4 * i];
            lb[i]   = (const float*)d_in[19 + 4 * i];
            gg[i]   = (const float*)d_in[20 + 4 * i];
            bb[i]   = (const float*)d_in[21 + 4 * i];
        }
    } else {
        for (int i = 0; i < 3; i++) {
            Wg[i]   = (const float*)d_in[3 + 9 * i];
            We[i]   = (const float*)d_in[4 + 9 * i];
            attn[i] = (const float*)d_in[5 + 9 * i];
            at[i]   = (const float*)d_in[6 + 9 * i];
            cb[i]   = (const float*)d_in[7 + 9 * i];
            lw[i]   = (const float*)d_in[8 + 9 * i];
            lb[i]   = (const float*)d_in[9 + 9 * i];
            gg[i]   = (const float*)d_in[10 + 9 * i];
            bb[i]   = (const float*)d_in[11 + 9 * i];
        }
    }

    Scratch S;
    cudaGetSymbolAddress((void**)&S.lin, g_lin);
    cudaGetSymbolAddress((void**)&S.hg, g_hg);
    cudaGetSymbolAddress((void**)&S.h, g_h);
    cudaGetSymbolAddress((void**)&S.logw, g_logw);
    cudaGetSymbolAddress((void**)&S.ssrc, g_ssrc);
    cudaGetSymbolAddress((void**)&S.sdst, g_sdst);
    cudaGetSymbolAddress((void**)&S.s1, g_s1);
    cudaGetSymbolAddress((void**)&S.s2, g_s2);
    cudaGetSymbolAddress((void**)&S.scale, g_scale);
    cudaGetSymbolAddress((void**)&S.shift, g_shift);
    cudaGetSymbolAddress((void**)&S.ve, g_ve);
    cudaGetSymbolAddress((void**)&S.deg, g_deg);
    cudaGetSymbolAddress((void**)&S.off, g_off);
    cudaGetSymbolAddress((void**)&S.cur, g_cur);
    cudaGetSymbolAddress((void**)&S.eid, g_eid);
    cudaGetSymbolAddress((void**)&S.Ah, g_Ah);
    cudaGetSymbolAddress((void**)&S.Al, g_Al);
    cudaGetSymbolAddress((void**)&S.B1h, g_B1h);
    cudaGetSymbolAddress((void**)&S.B1l, g_B1l);
    cudaGetSymbolAddress((void**)&S.B2h, g_B2h);
    cudaGetSymbolAddress((void**)&S.B2l, g_B2l);

    cudaFuncSetAttribute(gemm_mma, cudaFuncAttributeMaxDynamicSharedMemorySize, GT_SMEM);

    // ---- CSR by destination ----
    k_zero_i<<<cdiv(NN, 256), 256>>>(S.deg, NN);
    k_hist<<<cdiv(EE, 256), 256>>>(ei + EE, S.deg);
    k_scan<<<1, 1024>>>(S.deg, S.off, NN);
    k_zero_i<<<cdiv(NN, 256), 256>>>(S.cur, NN);
    k_scatter<<<cdiv(EE, 256), 256>>>(ei + EE, S.off, S.cur, S.eid);

    // ---- layers 1 & 2 ----
    run_big_layer(S, x,   F1,   192,  Wg[0], We[0], attn[0], at[0], cb[0], lw[0], lb[0], gg[0], bb[0], S.h, ei, ea);
    run_big_layer(S, S.h, HIDD, 1024, Wg[1], We[1], attn[1], at[1], cb[1], lw[1], lb[1], gg[1], bb[1], S.h, ei, ea);

    // ---- layer 3 ----
    k_zero_f<<<cdiv(HIDD, 256), 256>>>(S.s1, HIDD);
    k_zero_f<<<cdiv(HIDD, 256), 256>>>(S.s2, HIDD);
    k_bnstat<<<dim3(cdiv(HIDD, 256), 40), 256>>>(S.h, S.s1, S.s2, HIDD);
    k_bnfin<<<cdiv(HIDD, 256), 256>>>(S.s1, S.s2, gg[2], bb[2], S.scale, S.shift, HIDD);
    size_t ta = (size_t)NN * HIDD;
    k_prepA<<<(int)((ta + 255) / 256), 256>>>(S.h, S.scale, S.shift, S.Ah, S.Al, HIDD, HIDD);
    k_gemm_small<<<NN, 128>>>(S.Ah, S.Al, lw[2], Wg[2], S.lin, S.hg);
    k_ve<<<1, 64>>>(We[2], attn[2], S.ve, 1, 2);
    k_sdots<<<cdiv(NN * 1 * 32, 256), 256>>>(S.hg, attn[2], S.ssrc, S.sdst, 1, 2);
    k_logits<<<cdiv(EE * 1, 256), 256>>>(ei, ea, S.ssrc, S.sdst, S.ve, at[2], S.logw, 1);
    k_softmax<<<cdiv(NN * 1, 256), 256>>>(S.off, S.eid, S.logw, 1);
    k_agg_small<<<cdiv(NN, 256), 256>>>(S.hg, S.logw, S.off, S.eid, ea, ei, We[2], S.lin, lb[2], cb[2], (float*)d_out);
}

// round 7
// speedup vs baseline: 2.9720x; 1.0383x over previous
#include <cuda_runtime.h>
#include <cuda_bf16.h>
#include <cstdint>
#include <math.h>

#define NN   20000
#define EE   100000
#define F1   167
#define HIDD 1024
#define EDK  10
#define EAC  12

// ---------------- scratch (device globals) ----------------
__device__ float g_lin[(size_t)NN * HIDD];
__device__ float g_hg [(size_t)NN * HIDD];
__device__ float g_h  [(size_t)NN * HIDD];
__device__ float g_logw[(size_t)EE * 4];
__device__ float g_ssrc[(size_t)NN * 4];
__device__ float g_sdst[(size_t)NN * 4];
__device__ float g_s1[3][HIDD];
__device__ float g_s2[3][HIDD];
__device__ float g_scale[HIDD];
__device__ float g_shift[HIDD];
__device__ float g_ve[EDK * 4];
__device__ int   g_deg[NN];
__device__ int   g_off[NN + 1];
__device__ int   g_cur[NN];
__device__ int   g_eid[EE];
__device__ __nv_bfloat16 g_Ah[(size_t)NN * HIDD];
__device__ __nv_bfloat16 g_Al[(size_t)NN * HIDD];
__device__ __nv_bfloat16 g_B1h[(size_t)HIDD * HIDD];
__device__ __nv_bfloat16 g_B1l[(size_t)HIDD * HIDD];
__device__ __nv_bfloat16 g_B2h[(size_t)HIDD * HIDD];
__device__ __nv_bfloat16 g_B2l[(size_t)HIDD * HIDD];

// ---------------- init: zero everything once ----------------
__global__ void k_init(int* deg, int* cur, float* s1, float* s2) {
    int i = blockIdx.x * blockDim.x + threadIdx.x;
    if (i < NN) { deg[i] = 0; cur[i] = 0; }
    if (i < 3 * HIDD) { s1[i] = 0.f; s2[i] = 0.f; }
}

// ---------------- CSR build ----------------
__global__ void k_hist(const int* __restrict__ dst, int* __restrict__ deg) {
    int e = blockIdx.x * blockDim.x + threadIdx.x;
    if (e < EE) atomicAdd(&deg[dst[e]], 1);
}

__global__ void k_scan(const int* __restrict__ deg, int* __restrict__ off, int n) {
    __shared__ int sh[1024];
    __shared__ int carry;
    int t = threadIdx.x;
    if (t == 0) { carry = 0; off[0] = 0; }
    __syncthreads();
    for (int base = 0; base < n; base += 1024) {
        int v = (base + t < n) ? deg[base + t] : 0;
        sh[t] = v;
        __syncthreads();
        for (int d = 1; d < 1024; d <<= 1) {
            int add = (t >= d) ? sh[t - d] : 0;
            __syncthreads();
            sh[t] += add;
            __syncthreads();
        }
        if (base + t < n) off[base + t + 1] = carry + sh[t];
        __syncthreads();
        if (t == 0) carry += sh[1023];
        __syncthreads();
    }
}

__global__ void k_scatter(const int* __restrict__ dst, const int* __restrict__ off,
                          int* __restrict__ cur, int* __restrict__ eid) {
    int e = blockIdx.x * blockDim.x + threadIdx.x;
    if (e >= EE) return;
    int d = dst[e];
    int p = atomicAdd(&cur[d], 1);
    eid[off[d] + p] = e;
}

// ---------------- BatchNorm ----------------
__global__ void k_bnstat(const float* __restrict__ x, float* __restrict__ s1,
                         float* __restrict__ s2, int F) {
    int c = blockIdx.x * blockDim.x + threadIdx.x;
    if (c >= F) return;
    int nchunks = gridDim.y;
    int chunk = (NN + nchunks - 1) / nchunks;
    int r0 = blockIdx.y * chunk;
    int r1 = r0 + chunk; if (r1 > NN) r1 = NN;
    float a = 0.f, b = 0.f;
    for (int r = r0; r < r1; r++) {
        float v = x[(size_t)r * F + c];
        a += v; b += v * v;
    }
    atomicAdd(&s1[c], a);
    atomicAdd(&s2[c], b);
}

__global__ void k_bnfin(const float* __restrict__ s1, const float* __restrict__ s2,
                        const float* __restrict__ g, const float* __restrict__ b,
                        float* __restrict__ scale, float* __restrict__ shift, int F) {
    int c = blockIdx.x * blockDim.x + threadIdx.x;
    if (c >= F) return;
    float invN = 1.f / (float)NN;
    float mu = s1[c] * invN;
    float var = s2[c] * invN - mu * mu;
    float rstd = rsqrtf(var + 1e-5f);
    float sc = rstd * g[c];
    scale[c] = sc;
    shift[c] = b[c] - mu * sc;
}

// ---------------- bf16-split prep ----------------
__global__ void k_prepA(const float* __restrict__ x, const float* __restrict__ scale,
                        const float* __restrict__ shift,
                        __nv_bfloat16* __restrict__ Ah, __nv_bfloat16* __restrict__ Al,
                        int F, int Kp) {
    size_t i = (size_t)blockIdx.x * blockDim.x + threadIdx.x;
    if (i >= (size_t)NN * Kp) return;
    int m = (int)(i / Kp), k = (int)(i % Kp);
    float v = 0.f;
    if (k < F) v = x[(size_t)m * F + k] * scale[k] + shift[k];
    __nv_bfloat16 h = __float2bfloat16(v);
    float lo = v - __bfloat162float(h);
    Ah[i] = h;
    Al[i] = __float2bfloat16(lo);
}

// two weight matrices in one launch (blockIdx.y selects)
__global__ void k_prepB2(const float* __restrict__ W1, const float* __restrict__ W2,
                         __nv_bfloat16* __restrict__ B1h, __nv_bfloat16* __restrict__ B1l,
                         __nv_bfloat16* __restrict__ B2h, __nv_bfloat16* __restrict__ B2l,
                         int K, int Kp) {
    size_t i = (size_t)blockIdx.x * blockDim.x + threadIdx.x;
    if (i >= (size_t)HIDD * Kp) return;
    const float* W = blockIdx.y ? W2 : W1;
    __nv_bfloat16* Bh = blockIdx.y ? B2h : B1h;
    __nv_bfloat16* Bl = blockIdx.y ? B2l : B1l;
    int n = (int)(i / Kp), k = (int)(i % Kp);
    float v = (k < K) ? W[(size_t)k * HIDD + n] : 0.f;
    __nv_bfloat16 h = __float2bfloat16(v);
    float lo = v - __bfloat162float(h);
    Bh[i] = h;
    Bl[i] = __float2bfloat16(lo);
}

// ---------------- mma.sync helpers ----------------
__device__ __forceinline__ uint32_t smem_u32(const void* p) {
    uint32_t a;
    asm("{ .reg .u64 t; cvta.to.shared.u64 t, %1; cvt.u32.u64 %0, t; }" : "=r"(a) : "l"(p));
    return a;
}
__device__ __forceinline__ void sts128(uint32_t addr, uint4 v) {
    asm volatile("st.shared.v4.b32 [%0], {%1,%2,%3,%4};"
                 :: "r"(addr), "r"(v.x), "r"(v.y), "r"(v.z), "r"(v.w) : "memory");
}
__device__ __forceinline__ void cpasync16(uint32_t s, const void* g) {
    asm volatile("cp.async.cg.shared.global [%0], [%1], 16;" :: "r"(s), "l"(g));
}
#define CP_COMMIT() asm volatile("cp.async.commit_group;" ::: "memory")
#define CP_WAIT0()  asm volatile("cp.async.wait_group 0;" ::: "memory")
#define CP_WAIT1()  asm volatile("cp.async.wait_group 1;" ::: "memory")
#define SWZ(x) ((x) ^ (((x) >> 3) & 0x70))

#define LDSM4(r0, r1, r2, r3, addr) \
    asm volatile("ldmatrix.sync.aligned.m8n8.x4.shared.b16 {%0,%1,%2,%3}, [%4];" \
                 : "=r"(r0), "=r"(r1), "=r"(r2), "=r"(r3) : "r"(addr))

#define MMA_BF16(d, a0, a1, a2, a3, b0, b1) \
    asm volatile("mma.sync.aligned.m16n8k16.row.col.f32.bf16.bf16.f32 " \
                 "{%0,%1,%2,%3}, {%4,%5,%6,%7}, {%8,%9}, {%0,%1,%2,%3};" \
                 : "+f"((d)[0]), "+f"((d)[1]), "+f"((d)[2]), "+f"((d)[3]) \
                 : "r"(a0), "r"(a1), "r"(a2), "r"(a3), "r"(b0), "r"(b1))

// ---------------- split-bf16 GEMM, 3-stage single-sync pipeline ----------------
#define STAGE_BYTES 65536
#define GT_SMEM (3 * STAGE_BYTES + 1024)

__global__ __launch_bounds__(256, 1) void gemm_mma(
    const __nv_bfloat16* __restrict__ Ah, const __nv_bfloat16* __restrict__ Al, int Kp,
    const __nv_bfloat16* __restrict__ B1h, const __nv_bfloat16* __restrict__ B1l,
    const __nv_bfloat16* __restrict__ B2h, const __nv_bfloat16* __restrict__ B2l,
    float* __restrict__ C1, float* __restrict__ C2, int M)
{
    extern __shared__ char smraw[];
    uint32_t sb = (smem_u32(smraw) + 1023) & ~1023u;
    int tid = threadIdx.x, lane = tid & 31, wid = tid >> 5;
    int nt = blockIdx.x, mt = blockIdx.y;

    const __nv_bfloat16 *Bh, *Bl;
    float* C;
    int coloff;
    if (nt < 8) { Bh = B1h; Bl = B1l; C = C1; coloff = nt * 128; }
    else        { Bh = B2h; Bl = B2l; C = C2; coloff = (nt - 8) * 128; }

    int wm = wid & 1, wn = wid >> 1;   // 2 x 4 warp grid; warp tile 64x32

    float acc[4][4][4];
#pragma unroll
    for (int a = 0; a < 4; a++)
#pragma unroll
        for (int b = 0; b < 4; b++)
#pragma unroll
            for (int cc = 0; cc < 4; cc++) acc[a][b][cc] = 0.f;

    uint32_t offA[4][4];
    uint32_t offB[4][2];
#pragma unroll
    for (int mi = 0; mi < 4; mi++) {
        int row = wm * 64 + mi * 16 + (lane & 15);
#pragma unroll
        for (int k16 = 0; k16 < 4; k16++)
            offA[mi][k16] = SWZ((uint32_t)(row * 128 + k16 * 32 + (lane >> 4) * 16));
    }
#pragma unroll
    for (int p = 0; p < 2; p++) {
        int row = wn * 32 + p * 16 + ((lane >> 4) << 3) + (lane & 7);
#pragma unroll
        for (int k16 = 0; k16 < 4; k16++)
            offB[k16][p] = SWZ((uint32_t)(row * 128 + k16 * 32 + (((lane >> 3) & 1) << 4)));
    }

    int q = tid & 7;
    int rr = tid >> 3;
    int chunks = Kp >> 6;

    auto load_stage = [&](int c) {
        uint32_t base = sb + (uint32_t)(c % 3) * STAGE_BYTES;
        uint32_t bAh = base, bAl = base + 16384, bBh = base + 32768, bBl = base + 49152;
        size_t kel = (size_t)c * 64 + q * 8;
#pragma unroll
        for (int i = 0; i < 4; i++) {
            int row = rr + i * 32;
            uint32_t soff = SWZ((uint32_t)(row * 128 + q * 16));
            int m = mt * 128 + row;
            if (m < M) {
                cpasync16(bAh + soff, Ah + (size_t)m * Kp + kel);
                cpasync16(bAl + soff, Al + (size_t)m * Kp + kel);
            } else {
                uint4 z = make_uint4(0, 0, 0, 0);
                sts128(bAh + soff, z);
                sts128(bAl + soff, z);
            }
            int nr = coloff + row;
            cpasync16(bBh + soff, Bh + (size_t)nr * Kp + kel);
            cpasync16(bBl + soff, Bl + (size_t)nr * Kp + kel);
        }
        CP_COMMIT();
    };

    load_stage(0);
    if (chunks > 1) load_stage(1);

    for (int c = 0; c < chunks; c++) {
        if (c + 1 < chunks) { CP_WAIT1(); } else { CP_WAIT0(); }
        __syncthreads();
        // issue stage c+2 AFTER the barrier: its buffer (c+2)%3 == (c-1)%3 was
        // consumed in iteration c-1, and the barrier guarantees all warps are done.
        if (c + 2 < chunks) load_stage(c + 2);

        uint32_t cur = sb + (uint32_t)(c % 3) * STAGE_BYTES;
        uint32_t cAh = cur, cAl = cur + 16384, cBh = cur + 32768, cBl = cur + 49152;
#pragma unroll
        for (int k16 = 0; k16 < 4; k16++) {
            uint32_t ah0[4], ah1[4], ah2[4], ah3[4];
            uint32_t al0[4], al1[4], al2[4], al3[4];
#pragma unroll
            for (int mi = 0; mi < 4; mi++) {
                LDSM4(ah0[mi], ah1[mi], ah2[mi], ah3[mi], cAh + offA[mi][k16]);
                LDSM4(al0[mi], al1[mi], al2[mi], al3[mi], cAl + offA[mi][k16]);
            }
            uint32_t bh0[4], bh1[4], bl0[4], bl1[4];
#pragma unroll
            for (int pp = 0; pp < 2; pp++) {
                uint32_t r0_, r1_, r2_, r3_;
                LDSM4(r0_, r1_, r2_, r3_, cBh + offB[k16][pp]);
                bh0[pp * 2] = r0_; bh1[pp * 2] = r1_;
                bh0[pp * 2 + 1] = r2_; bh1[pp * 2 + 1] = r3_;
                LDSM4(r0_, r1_, r2_, r3_, cBl + offB[k16][pp]);
                bl0[pp * 2] = r0_; bl1[pp * 2] = r1_;
                bl0[pp * 2 + 1] = r2_; bl1[pp * 2 + 1] = r3_;
            }
#pragma unroll
            for (int mi = 0; mi < 4; mi++) {
#pragma unroll
                for (int ni = 0; ni < 4; ni++) {
                    MMA_BF16(acc[mi][ni], ah0[mi], ah1[mi], ah2[mi], ah3[mi], bh0[ni], bh1[ni]);
                    MMA_BF16(acc[mi][ni], ah0[mi], ah1[mi], ah2[mi], ah3[mi], bl0[ni], bl1[ni]);
                    MMA_BF16(acc[mi][ni], al0[mi], al1[mi], al2[mi], al3[mi], bh0[ni], bh1[ni]);
                }
            }
        }
    }

    // epilogue
#pragma unroll
    for (int mi = 0; mi < 4; mi++) {
        int gr = mt * 128 + wm * 64 + mi * 16 + (lane >> 2);
#pragma unroll
        for (int ni = 0; ni < 4; ni++) {
            int gc = coloff + wn * 32 + ni * 8 + ((lane & 3) << 1);
            if (gr < M)
                *(float2*)(C + (size_t)gr * HIDD + gc) = make_float2(acc[mi][ni][0], acc[mi][ni][1]);
            if (gr + 8 < M)
                *(float2*)(C + (size_t)(gr + 8) * HIDD + gc) = make_float2(acc[mi][ni][2], acc[mi][ni][3]);
        }
    }
}

// ---------------- layer-3 tiny GEMM (reads h + BN inline, fp32) ----------------
__global__ __launch_bounds__(128) void k_gemm_small(
    const float* __restrict__ h, const float* __restrict__ scale,
    const float* __restrict__ shift,
    const float* __restrict__ lw, const float* __restrict__ wg,
    float* __restrict__ lin, float* __restrict__ hg)
{
    int n = blockIdx.x, t = threadIdx.x;
    const float* hr = h + (size_t)n * HIDD;
    float a0 = 0, a1 = 0, a2 = 0, a3 = 0;
    for (int k = t; k < HIDD; k += 128) {
        float a = hr[k] * scale[k] + shift[k];
        a0 += a * lw[k * 2];
        a1 += a * lw[k * 2 + 1];
        a2 += a * wg[k * 2];
        a3 += a * wg[k * 2 + 1];
    }
#pragma unroll
    for (int s = 16; s; s >>= 1) {
        a0 += __shfl_down_sync(0xFFFFFFFFu, a0, s);
        a1 += __shfl_down_sync(0xFFFFFFFFu, a1, s);
        a2 += __shfl_down_sync(0xFFFFFFFFu, a2, s);
        a3 += __shfl_down_sync(0xFFFFFFFFu, a3, s);
    }
    __shared__ float sm[4][4];
    if ((t & 31) == 0) {
        sm[t >> 5][0] = a0; sm[t >> 5][1] = a1; sm[t >> 5][2] = a2; sm[t >> 5][3] = a3;
    }
    __syncthreads();
    if (t == 0) {
        lin[(size_t)n * 2]     = sm[0][0] + sm[1][0] + sm[2][0] + sm[3][0];
        lin[(size_t)n * 2 + 1] = sm[0][1] + sm[1][1] + sm[2][1] + sm[3][1];
        hg [(size_t)n * 2]     = sm[0][2] + sm[1][2] + sm[2][2] + sm[3][2];
        hg [(size_t)n * 2 + 1] = sm[0][3] + sm[1][3] + sm[2][3] + sm[3][3];
    }
}

// ---------------- GAT pieces ----------------
__global__ void k_ve(const float* __restrict__ We, const float* __restrict__ attn,
                     float* __restrict__ ve, int H, int O) {
    int t = threadIdx.x;
    if (t >= H * EDK) return;
    int h = t / EDK, k = t % EDK;
    const float* a2 = attn + (size_t)(2 * H + h) * O;
    const float* w = We + (size_t)k * H * O + (size_t)h * O;
    float s = 0.f;
    for (int d = 0; d < O; d++) s += w[d] * a2[d];
    ve[k * H + h] = s;
}

__global__ void k_sdots(const float* __restrict__ hg, const float* __restrict__ attn,
                        float* __restrict__ ssrc, float* __restrict__ sdst, int H, int O) {
    int gw = (blockIdx.x * blockDim.x + threadIdx.x) >> 5;
    int lane = threadIdx.x & 31;
    if (gw >= NN * H) return;
    int n = gw / H, h = gw % H;
    const float* hr = hg + (size_t)n * H * O + (size_t)h * O;
    const float* a0 = attn + (size_t)h * O;
    const float* a1 = attn + (size_t)(H + h) * O;
    float d0 = 0.f, d1 = 0.f;
    for (int d = lane; d < O; d += 32) {
        float v = hr[d];
        d0 += v * a0[d];
        d1 += v * a1[d];
    }
#pragma unroll
    for (int s = 16; s; s >>= 1) {
        d0 += __shfl_down_sync(0xFFFFFFFFu, d0, s);
        d1 += __shfl_down_sync(0xFFFFFFFFu, d1, s);
    }
    if (lane == 0) { ssrc[gw] = d0; sdst[gw] = d1; }
}

__global__ void k_logits(const int* __restrict__ ei, const float* __restrict__ ea,
                         const float* __restrict__ ssrc, const float* __restrict__ sdst,
                         const float* __restrict__ ve, const float* __restrict__ at,
                         float* __restrict__ logw, int H) {
    int idx = blockIdx.x * blockDim.x + threadIdx.x;
    if (idx >= EE * H) return;
    int e = idx / H, h = idx % H;
    int s = ei[e], d = ei[EE + e];
    const float* row = ea + (size_t)e * EAC;
    float t = row[0];
    float se = 0.f;
#pragma unroll
    for (int k = 0; k < EDK; k++) se += row[1 + k] * ve[k * H + h];
    float l = ssrc[s * H + h] + sdst[d * H + h] + se + t * at[h];
    logw[idx] = (l > 0.f) ? l : 0.2f * l;
}

// softmax per dst node, all 4 heads via float4
__global__ void k_softmax4(const int* __restrict__ off, const int* __restrict__ eid,
                           float4* __restrict__ w4) {
    int n = blockIdx.x * blockDim.x + threadIdx.x;
    if (n >= NN) return;
    int d0 = off[n], d1 = off[n + 1];
    if (d0 == d1) return;
    float4 m = make_float4(-INFINITY, -INFINITY, -INFINITY, -INFINITY);
    for (int i = d0; i < d1; i++) {
        float4 v = w4[eid[i]];
        m.x = fmaxf(m.x, v.x); m.y = fmaxf(m.y, v.y);
        m.z = fmaxf(m.z, v.z); m.w = fmaxf(m.w, v.w);
    }
    float4 s = make_float4(0.f, 0.f, 0.f, 0.f);
    for (int i = d0; i < d1; i++) {
        float4 v = w4[eid[i]];
        v.x = expf(v.x - m.x); v.y = expf(v.y - m.y);
        v.z = expf(v.z - m.z); v.w = expf(v.w - m.w);
        w4[eid[i]] = v;
        s.x += v.x; s.y += v.y; s.z += v.z; s.w += v.w;
    }
    float4 inv = make_float4(1.f / (s.x + 1e-16f), 1.f / (s.y + 1e-16f),
                             1.f / (s.z + 1e-16f), 1.f / (s.w + 1e-16f));
    for (int i = d0; i < d1; i++) {
        float4 v = w4[eid[i]];
        v.x *= inv.x; v.y *= inv.y; v.z *= inv.z; v.w *= inv.w;
        w4[eid[i]] = v;
    }
}

__global__ void k_softmax1(const int* __restrict__ off, const int* __restrict__ eid,
                           float* __restrict__ logw) {
    int n = blockIdx.x * blockDim.x + threadIdx.x;
    if (n >= NN) return;
    int d0 = off[n], d1 = off[n + 1];
    if (d0 == d1) return;
    float m = -INFINITY;
    for (int i = d0; i < d1; i++) m = fmaxf(m, logw[eid[i]]);
    float s = 0.f;
    for (int i = d0; i < d1; i++) {
        float p = expf(logw[eid[i]] - m);
        logw[eid[i]] = p;
        s += p;
    }
    float inv = 1.f / (s + 1e-16f);
    for (int i = d0; i < d1; i++) logw[eid[i]] *= inv;
}

__global__ __launch_bounds__(256) void k_agg_big(
    const float* __restrict__ hg, const float* __restrict__ w,
    const int* __restrict__ off, const int* __restrict__ eid,
    const float* __restrict__ ea, const int* __restrict__ src,
    const float* __restrict__ We, const float* __restrict__ lin,
    const float* __restrict__ lb, const float* __restrict__ cb,
    float* __restrict__ out)
{
    int n = blockIdx.x;
    int t = threadIdx.x;
    __shared__ float qs[40];
    if (t < 40) qs[t] = 0.f;
    float acc0 = 0.f, acc1 = 0.f, acc2 = 0.f, acc3 = 0.f;
    int d0 = off[n], d1 = off[n + 1];
    for (int i = d0; i < d1; i++) {
        int e = eid[i];
        int s = src[e];
        float4 wv = *(const float4*)(w + (size_t)e * 4);
        const float* hr = hg + (size_t)s * 1024;
        acc0 += wv.x * hr[t];
        acc1 += wv.y * hr[t + 256];
        acc2 += wv.z * hr[t + 512];
        acc3 += wv.w * hr[t + 768];
        if (t < 40) {
            int h = t / 10, k = t % 10;
            float wh = (h == 0) ? wv.x : (h == 1) ? wv.y : (h == 2) ? wv.z : wv.w;
            qs[t] += wh * ea[(size_t)e * EAC + 1 + k];
        }
    }
    __syncthreads();
    float acch[4] = {acc0, acc1, acc2, acc3};
#pragma unroll
    for (int h = 0; h < 4; h++) {
        int f = h * 256 + t;
        float et = 0.f;
#pragma unroll
        for (int k = 0; k < 10; k++) et += qs[h * 10 + k] * We[k * 1024 + f];
        float v = lin[(size_t)n * 1024 + f] + lb[f] + cb[f] + acch[h] + et;
        out[(size_t)n * 1024 + f] = fmaxf(v, 0.f);
    }
}

__global__ void k_agg_small(
    const float* __restrict__ hg, const float* __restrict__ w,
    const int* __restrict__ off, const int* __restrict__ eid,
    const float* __restrict__ ea, const int* __restrict__ src,
    const float* __restrict__ We, const float* __restrict__ lin,
    const float* __restrict__ lb, const float* __restrict__ cb,
    float* __restrict__ out)
{
    int n = blockIdx.x * blockDim.x + threadIdx.x;
    if (n >= NN) return;
    float a0 = 0.f, a1 = 0.f;
    float q[10];
#pragma unroll
    for (int k = 0; k < 10; k++) q[k] = 0.f;
    int d0 = off[n], d1 = off[n + 1];
    for (int i = d0; i < d1; i++) {
        int e = eid[i];
        int s = src[e];
        float wv = w[e];
        a0 += wv * hg[(size_t)s * 2];
        a1 += wv * hg[(size_t)s * 2 + 1];
        const float* row = ea + (size_t)e * EAC;
#pragma unroll
        for (int k = 0; k < 10; k++) q[k] += wv * row[1 + k];
    }
    float e0 = 0.f, e1 = 0.f;
#pragma unroll
    for (int k = 0; k < 10; k++) { e0 += q[k] * We[k * 2]; e1 += q[k] * We[k * 2 + 1]; }
    float v0 = lin[(size_t)n * 2] + lb[0] + cb[0] + a0 + e0;
    float v1 = lin[(size_t)n * 2 + 1] + lb[1] + cb[1] + a1 + e1;
    out[(size_t)n * 2] = fmaxf(v0, 0.f);
    out[(size_t)n * 2 + 1] = fmaxf(v1, 0.f);
}

// ---------------- host driver ----------------
static inline int cdiv(int a, int b) { return (a + b - 1) / b; }

struct Scratch {
    float *lin, *hg, *h, *logw, *ssrc, *sdst, *scale, *shift, *ve;
    float *s1, *s2;  // base of [3][HIDD]
    int *deg, *off, *cur, *eid;
    __nv_bfloat16 *Ah, *Al, *B1h, *B1l, *B2h, *B2l;
};

static void run_big_layer(const Scratch& S, int li, const float* xin, int F, int Kp,
                          const float* Wg, const float* We, const float* attn,
                          const float* at, const float* cb,
                          const float* lw, const float* lb,
                          const float* g, const float* b,
                          float* out, const int* ei, const float* ea)
{
    const int H = 4, O = 256;
    float* s1 = S.s1 + li * HIDD;
    float* s2 = S.s2 + li * HIDD;
    k_bnstat<<<dim3(cdiv(F, 256), 40), 256>>>(xin, s1, s2, F);
    k_bnfin<<<cdiv(F, 256), 256>>>(s1, s2, g, b, S.scale, S.shift, F);
    size_t ta = (size_t)NN * Kp;
    k_prepA<<<(int)((ta + 255) / 256), 256>>>(xin, S.scale, S.shift, S.Ah, S.Al, F, Kp);
    size_t tb = (size_t)HIDD * Kp;
    k_prepB2<<<dim3((int)((tb + 255) / 256), 2), 256>>>(lw, Wg, S.B1h, S.B1l, S.B2h, S.B2l, F, Kp);
    gemm_mma<<<dim3(16, cdiv(NN, 128)), 256, GT_SMEM>>>(
        S.Ah, S.Al, Kp, S.B1h, S.B1l, S.B2h, S.B2l, S.lin, S.hg, NN);
    k_ve<<<1, 64>>>(We, attn, S.ve, H, O);
    k_sdots<<<cdiv(NN * H * 32, 256), 256>>>(S.hg, attn, S.ssrc, S.sdst, H, O);
    k_logits<<<cdiv(EE * H, 256), 256>>>(ei, ea, S.ssrc, S.sdst, S.ve, at, S.logw, H);
    k_softmax4<<<cdiv(NN, 256), 256>>>(S.off, S.eid, (float4*)S.logw);
    k_agg_big<<<NN, 256>>>(S.hg, S.logw, S.off, S.eid, ea, ei, We, S.lin, lb, cb, out);
}

extern "C" void kernel_launch(void* const* d_in, const int* in_sizes, int n_in,
                              void* d_out, int out_size)
{
    const float* x  = (const float*)d_in[0];
    const int*   ei = (const int*)d_in[1];
    const float* ea = (const float*)d_in[2];

    const float *Wg[3], *We[3], *attn[3], *at[3], *cb[3];
    const float *lw[3], *lb[3], *gg[3], *bb[3];

    if (in_sizes[8] == 1048576) {
        for (int i = 0; i < 3; i++) {
            Wg[i]   = (const float*)d_in[3 + 5 * i];
            We[i]   = (const float*)d_in[4 + 5 * i];
            attn[i] = (const float*)d_in[5 + 5 * i];
            at[i]   = (const float*)d_in[6 + 5 * i];
            cb[i]   = (const float*)d_in[7 + 5 * i];
            lw[i]   = (const float*)d_in[18 + 4 * i];
            lb[i]   = (const float*)d_in[19 + 4 * i];
            gg[i]   = (const float*)d_in[20 + 4 * i];
            bb[i]   = (const float*)d_in[21 + 4 * i];
        }
    } else {
        for (int i = 0; i < 3; i++) {
            Wg[i]   = (const float*)d_in[3 + 9 * i];
            We[i]   = (const float*)d_in[4 + 9 * i];
            attn[i] = (const float*)d_in[5 + 9 * i];
            at[i]   = (const float*)d_in[6 + 9 * i];
            cb[i]   = (const float*)d_in[7 + 9 * i];
            lw[i]   = (const float*)d_in[8 + 9 * i];
            lb[i]   = (const float*)d_in[9 + 9 * i];
            gg[i]   = (const float*)d_in[10 + 9 * i];
            bb[i]   = (const float*)d_in[11 + 9 * i];
        }
    }

    Scratch S;
    cudaGetSymbolAddress((void**)&S.lin, g_lin);
    cudaGetSymbolAddress((void**)&S.hg, g_hg);
    cudaGetSymbolAddress((void**)&S.h, g_h);
    cudaGetSymbolAddress((void**)&S.logw, g_logw);
    cudaGetSymbolAddress((void**)&S.ssrc, g_ssrc);
    cudaGetSymbolAddress((void**)&S.sdst, g_sdst);
    cudaGetSymbolAddress((void**)&S.s1, g_s1);
    cudaGetSymbolAddress((void**)&S.s2, g_s2);
    cudaGetSymbolAddress((void**)&S.scale, g_scale);
    cudaGetSymbolAddress((void**)&S.shift, g_shift);
    cudaGetSymbolAddress((void**)&S.ve, g_ve);
    cudaGetSymbolAddress((void**)&S.deg, g_deg);
    cudaGetSymbolAddress((void**)&S.off, g_off);
    cudaGetSymbolAddress((void**)&S.cur, g_cur);
    cudaGetSymbolAddress((void**)&S.eid, g_eid);
    cudaGetSymbolAddress((void**)&S.Ah, g_Ah);
    cudaGetSymbolAddress((void**)&S.Al, g_Al);
    cudaGetSymbolAddress((void**)&S.B1h, g_B1h);
    cudaGetSymbolAddress((void**)&S.B1l, g_B1l);
    cudaGetSymbolAddress((void**)&S.B2h, g_B2h);
    cudaGetSymbolAddress((void**)&S.B2l, g_B2l);

    cudaFuncSetAttribute(gemm_mma, cudaFuncAttributeMaxDynamicSharedMemorySize, GT_SMEM);

    // ---- init + CSR ----
    k_init<<<cdiv(NN, 256), 256>>>(S.deg, S.cur, S.s1, S.s2);
    k_hist<<<cdiv(EE, 256), 256>>>(ei + EE, S.deg);
    k_scan<<<1, 1024>>>(S.deg, S.off, NN);
    k_scatter<<<cdiv(EE, 256), 256>>>(ei + EE, S.off, S.cur, S.eid);

    // ---- layers 1 & 2 ----
    run_big_layer(S, 0, x,   F1,   192,  Wg[0], We[0], attn[0], at[0], cb[0], lw[0], lb[0], gg[0], bb[0], S.h, ei, ea);
    run_big_layer(S, 1, S.h, HIDD, 1024, Wg[1], We[1], attn[1], at[1], cb[1], lw[1], lb[1], gg[1], bb[1], S.h, ei, ea);

    // ---- layer 3 (BN inline in k_gemm_small; no prepA) ----
    float* s1 = S.s1 + 2 * HIDD;
    float* s2 = S.s2 + 2 * HIDD;
    k_bnstat<<<dim3(cdiv(HIDD, 256), 40), 256>>>(S.h, s1, s2, HIDD);
    k_bnfin<<<cdiv(HIDD, 256), 256>>>(s1, s2, gg[2], bb[2], S.scale, S.shift, HIDD);
    k_gemm_small<<<NN, 128>>>(S.h, S.scale, S.shift, lw[2], Wg[2], S.lin, S.hg);
    k_ve<<<1, 64>>>(We[2], attn[2], S.ve, 1, 2);
    k_sdots<<<cdiv(NN * 1 * 32, 256), 256>>>(S.hg, attn[2], S.ssrc, S.sdst, 1, 2);
    k_logits<<<cdiv(EE * 1, 256), 256>>>(ei, ea, S.ssrc, S.sdst, S.ve, at[2], S.logw, 1);
    k_softmax1<<<cdiv(NN, 256), 256>>>(S.off, S.eid, S.logw);
    k_agg_small<<<cdiv(NN, 256), 256>>>(S.hg, S.logw, S.off, S.eid, ea, ei, We[2], S.lin, lb[2], cb[2], (float*)d_out);
}

// round 8
// speedup vs baseline: 2.9725x; 1.0001x over previous
#include <cuda_runtime.h>
#include <cuda_bf16.h>
#include <cstdint>
#include <math.h>

#define NN   20000
#define EE   100000
#define F1   167
#define HIDD 1024
#define EDK  10
#define EAC  12
#define BNCH 40

// ---------------- scratch (device globals) ----------------
__device__ float g_lin[(size_t)NN * HIDD];
__device__ float g_hg [(size_t)NN * HIDD];
__device__ float g_h  [(size_t)NN * HIDD];
__device__ float g_logw[(size_t)EE * 4];
__device__ float g_ssrc[(size_t)NN * 4];
__device__ float g_sdst[(size_t)NN * 4];
__device__ float g_part1[BNCH * HIDD];
__device__ float g_part2[BNCH * HIDD];
__device__ float g_scale[HIDD];
__device__ float g_shift[HIDD];
__device__ float g_ve[EDK * 4];
__device__ int   g_deg[NN];
__device__ int   g_off[NN + 1];
__device__ int   g_cur[NN];
__device__ int   g_eid[EE];
__device__ __nv_bfloat16 g_Ah[(size_t)NN * HIDD];
__device__ __nv_bfloat16 g_Al[(size_t)NN * HIDD];
__device__ __nv_bfloat16 g_B1h[(size_t)HIDD * HIDD];
__device__ __nv_bfloat16 g_B1l[(size_t)HIDD * HIDD];
__device__ __nv_bfloat16 g_B2h[(size_t)HIDD * HIDD];
__device__ __nv_bfloat16 g_B2l[(size_t)HIDD * HIDD];

// ---------------- BatchNorm: partials (no pre-zero needed) ----------------
__global__ void k_bnstat(const float* __restrict__ x, float* __restrict__ p1,
                         float* __restrict__ p2, int F) {
    int c = blockIdx.x * blockDim.x + threadIdx.x;
    if (c >= F) return;
    int chunk = (NN + BNCH - 1) / BNCH;
    int r0 = blockIdx.y * chunk;
    int r1 = r0 + chunk; if (r1 > NN) r1 = NN;
    float a = 0.f, b = 0.f;
    for (int r = r0; r < r1; r++) {
        float v = x[(size_t)r * F + c];
        a += v; b += v * v;
    }
    p1[blockIdx.y * F + c] = a;
    p2[blockIdx.y * F + c] = b;
}

__global__ void k_bnfin(const float* __restrict__ p1, const float* __restrict__ p2,
                        const float* __restrict__ g, const float* __restrict__ b,
                        float* __restrict__ scale, float* __restrict__ shift, int F) {
    int c = blockIdx.x * blockDim.x + threadIdx.x;
    if (c >= F) return;
    float a = 0.f, s = 0.f;
    for (int y = 0; y < BNCH; y++) { a += p1[y * F + c]; s += p2[y * F + c]; }
    float invN = 1.f / (float)NN;
    float mu = a * invN;
    float var = s * invN - mu * mu;
    float rstd = rsqrtf(var + 1e-5f);
    float sc = rstd * g[c];
    scale[c] = sc;
    shift[c] = b[c] - mu * sc;
}

// ---------------- fused prep: A-split + both B-splits in ONE launch ----------------
__global__ void k_prep(const float* __restrict__ x, const float* __restrict__ scale,
                       const float* __restrict__ shift,
                       __nv_bfloat16* __restrict__ Ah, __nv_bfloat16* __restrict__ Al,
                       const float* __restrict__ W1, const float* __restrict__ W2,
                       __nv_bfloat16* __restrict__ B1h, __nv_bfloat16* __restrict__ B1l,
                       __nv_bfloat16* __restrict__ B2h, __nv_bfloat16* __restrict__ B2l,
                       int F, int Kp) {
    size_t na = (size_t)NN * Kp;
    size_t nb = (size_t)HIDD * Kp;
    size_t i = (size_t)blockIdx.x * blockDim.x + threadIdx.x;
    if (i < na) {
        int m = (int)(i / Kp), k = (int)(i % Kp);
        float v = 0.f;
        if (k < F) v = x[(size_t)m * F + k] * scale[k] + shift[k];
        __nv_bfloat16 h = __float2bfloat16(v);
        Ah[i] = h;
        Al[i] = __float2bfloat16(v - __bfloat162float(h));
    } else if (i < na + 2 * nb) {
        size_t j = i - na;
        const float* W = (j < nb) ? W1 : W2;
        __nv_bfloat16* Bh = (j < nb) ? B1h : B2h;
        __nv_bfloat16* Bl = (j < nb) ? B1l : B2l;
        if (j >= nb) j -= nb;
        int n = (int)(j / Kp), k = (int)(j % Kp);
        float v = (k < F) ? W[(size_t)k * HIDD + n] : 0.f;
        __nv_bfloat16 h = __float2bfloat16(v);
        Bh[j] = h;
        Bl[j] = __float2bfloat16(v - __bfloat162float(h));
    }
}

// ---------------- mma.sync helpers ----------------
__device__ __forceinline__ uint32_t smem_u32(const void* p) {
    uint32_t a;
    asm("{ .reg .u64 t; cvta.to.shared.u64 t, %1; cvt.u32.u64 %0, t; }" : "=r"(a) : "l"(p));
    return a;
}
__device__ __forceinline__ void sts128(uint32_t addr, uint4 v) {
    asm volatile("st.shared.v4.b32 [%0], {%1,%2,%3,%4};"
                 :: "r"(addr), "r"(v.x), "r"(v.y), "r"(v.z), "r"(v.w) : "memory");
}
__device__ __forceinline__ void cpasync16(uint32_t s, const void* g) {
    asm volatile("cp.async.cg.shared.global [%0], [%1], 16;" :: "r"(s), "l"(g));
}
#define CP_COMMIT() asm volatile("cp.async.commit_group;" ::: "memory")
#define CP_WAIT0()  asm volatile("cp.async.wait_group 0;" ::: "memory")
#define SWZ(x) ((x) ^ (((x) >> 3) & 0x70))

#define LDSM4(r0, r1, r2, r3, addr) \
    asm volatile("ldmatrix.sync.aligned.m8n8.x4.shared.b16 {%0,%1,%2,%3}, [%4];" \
                 : "=r"(r0), "=r"(r1), "=r"(r2), "=r"(r3) : "r"(addr))

#define MMA_BF16(d, a0, a1, a2, a3, b0, b1) \
    asm volatile("mma.sync.aligned.m16n8k16.row.col.f32.bf16.bf16.f32 " \
                 "{%0,%1,%2,%3}, {%4,%5,%6,%7}, {%8,%9}, {%0,%1,%2,%3};" \
                 : "+f"((d)[0]), "+f"((d)[1]), "+f"((d)[2]), "+f"((d)[3]) \
                 : "r"(a0), "r"(a1), "r"(a2), "r"(a3), "r"(b0), "r"(b1))

// ---------------- split-bf16 GEMM: 128x256 CTA tile, 2-stage pipeline ----------------
// grid.x = 8 n-tiles: 0-3 -> (B1 -> C1), 4-7 -> (B2 -> C2). C = A @ B^T.
#define STAGE_BYTES 98304   // A: 2*16KB, B: 2*32KB
#define GT_SMEM (2 * STAGE_BYTES + 1024)

__global__ __launch_bounds__(256, 1) void gemm_mma(
    const __nv_bfloat16* __restrict__ Ah, const __nv_bfloat16* __restrict__ Al, int Kp,
    const __nv_bfloat16* __restrict__ B1h, const __nv_bfloat16* __restrict__ B1l,
    const __nv_bfloat16* __restrict__ B2h, const __nv_bfloat16* __restrict__ B2l,
    float* __restrict__ C1, float* __restrict__ C2, int M)
{
    extern __shared__ char smraw[];
    uint32_t sb = (smem_u32(smraw) + 1023) & ~1023u;
    int tid = threadIdx.x, lane = tid & 31, wid = tid >> 5;
    int nt = blockIdx.x, mt = blockIdx.y;

    const __nv_bfloat16 *Bh, *Bl;
    float* C;
    int coloff;
    if (nt < 4) { Bh = B1h; Bl = B1l; C = C1; coloff = nt * 256; }
    else        { Bh = B2h; Bl = B2l; C = C2; coloff = (nt - 4) * 256; }

    int wm = wid & 1, wn = wid >> 1;   // 2 x 4 warp grid; warp tile 64x64

    float acc[4][8][4];
#pragma unroll
    for (int a = 0; a < 4; a++)
#pragma unroll
        for (int b = 0; b < 8; b++)
#pragma unroll
            for (int cc = 0; cc < 4; cc++) acc[a][b][cc] = 0.f;

    uint32_t offA[4][4];   // [mi][k16] within 16KB A region
    uint32_t offB[4][4];   // [k16][pp]  within 32KB B region
#pragma unroll
    for (int mi = 0; mi < 4; mi++) {
        int row = wm * 64 + mi * 16 + (lane & 15);
#pragma unroll
        for (int k16 = 0; k16 < 4; k16++)
            offA[mi][k16] = SWZ((uint32_t)(row * 128 + k16 * 32 + (lane >> 4) * 16));
    }
#pragma unroll
    for (int p = 0; p < 4; p++) {
        int row = wn * 64 + p * 16 + ((lane >> 4) << 3) + (lane & 7);
#pragma unroll
        for (int k16 = 0; k16 < 4; k16++)
            offB[k16][p] = SWZ((uint32_t)(row * 128 + k16 * 32 + (((lane >> 3) & 1) << 4)));
    }

    int q = tid & 7;
    int rr = tid >> 3;
    int chunks = Kp >> 6;

    auto load_stage = [&](int c) {
        uint32_t base = sb + (uint32_t)(c & 1) * STAGE_BYTES;
        uint32_t bAh = base, bAl = base + 16384, bBh = base + 32768, bBl = base + 65536;
        size_t kel = (size_t)c * 64 + q * 8;
#pragma unroll
        for (int i = 0; i < 4; i++) {
            int row = rr + i * 32;
            uint32_t soff = SWZ((uint32_t)(row * 128 + q * 16));
            int m = mt * 128 + row;
            if (m < M) {
                cpasync16(bAh + soff, Ah + (size_t)m * Kp + kel);
                cpasync16(bAl + soff, Al + (size_t)m * Kp + kel);
            } else {
                uint4 z = make_uint4(0, 0, 0, 0);
                sts128(bAh + soff, z);
                sts128(bAl + soff, z);
            }
        }
#pragma unroll
        for (int i = 0; i < 8; i++) {
            int row = rr + i * 32;
            uint32_t soff = SWZ((uint32_t)(row * 128 + q * 16));
            int nr = coloff + row;
            cpasync16(bBh + soff, Bh + (size_t)nr * Kp + kel);
            cpasync16(bBl + soff, Bl + (size_t)nr * Kp + kel);
        }
        CP_COMMIT();
    };

    load_stage(0);

    for (int c = 0; c < chunks; c++) {
        CP_WAIT0();
        __syncthreads();                 // stage c ready; buffer (c+1)&1 free
        if (c + 1 < chunks) load_stage(c + 1);

        uint32_t cur = sb + (uint32_t)(c & 1) * STAGE_BYTES;
        uint32_t cAh = cur, cAl = cur + 16384, cBh = cur + 32768, cBl = cur + 65536;
#pragma unroll
        for (int k16 = 0; k16 < 4; k16++) {
            uint32_t bh0[8], bh1[8], bl0[8], bl1[8];
#pragma unroll
            for (int pp = 0; pp < 4; pp++) {
                uint32_t r0_, r1_, r2_, r3_;
                LDSM4(r0_, r1_, r2_, r3_, cBh + offB[k16][pp]);
                bh0[pp * 2] = r0_; bh1[pp * 2] = r1_;
                bh0[pp * 2 + 1] = r2_; bh1[pp * 2 + 1] = r3_;
                LDSM4(r0_, r1_, r2_, r3_, cBl + offB[k16][pp]);
                bl0[pp * 2] = r0_; bl1[pp * 2] = r1_;
                bl0[pp * 2 + 1] = r2_; bl1[pp * 2 + 1] = r3_;
            }
#pragma unroll
            for (int mi = 0; mi < 4; mi++) {
                uint32_t a0, a1, a2, a3, l0, l1, l2, l3;
                LDSM4(a0, a1, a2, a3, cAh + offA[mi][k16]);
                LDSM4(l0, l1, l2, l3, cAl + offA[mi][k16]);
#pragma unroll
                for (int ni = 0; ni < 8; ni++) {
                    MMA_BF16(acc[mi][ni], a0, a1, a2, a3, bh0[ni], bh1[ni]);
                    MMA_BF16(acc[mi][ni], a0, a1, a2, a3, bl0[ni], bl1[ni]);
                    MMA_BF16(acc[mi][ni], l0, l1, l2, l3, bh0[ni], bh1[ni]);
                }
            }
        }
    }

    // epilogue
#pragma unroll
    for (int mi = 0; mi < 4; mi++) {
        int gr = mt * 128 + wm * 64 + mi * 16 + (lane >> 2);
#pragma unroll
        for (int ni = 0; ni < 8; ni++) {
            int gc = coloff + wn * 64 + ni * 8 + ((lane & 3) << 1);
            if (gr < M)
                *(float2*)(C + (size_t)gr * HIDD + gc) = make_float2(acc[mi][ni][0], acc[mi][ni][1]);
            if (gr + 8 < M)
                *(float2*)(C + (size_t)(gr + 8) * HIDD + gc) = make_float2(acc[mi][ni][2], acc[mi][ni][3]);
        }
    }
}

// ---------------- CSR build ----------------
__global__ void k_init(int* deg, int* cur) {
    int i = blockIdx.x * blockDim.x + threadIdx.x;
    if (i < NN) { deg[i] = 0; cur[i] = 0; }
}
__global__ void k_hist(const int* __restrict__ dst, int* __restrict__ deg) {
    int e = blockIdx.x * blockDim.x + threadIdx.x;
    if (e < EE) atomicAdd(&deg[dst[e]], 1);
}
__global__ void k_scan(const int* __restrict__ deg, int* __restrict__ off, int n) {
    __shared__ int sh[1024];
    __shared__ int carry;
    int t = threadIdx.x;
    if (t == 0) { carry = 0; off[0] = 0; }
    __syncthreads();
    for (int base = 0; base < n; base += 1024) {
        int v = (base + t < n) ? deg[base + t] : 0;
        sh[t] = v;
        __syncthreads();
        for (int d = 1; d < 1024; d <<= 1) {
            int add = (t >= d) ? sh[t - d] : 0;
            __syncthreads();
            sh[t] += add;
            __syncthreads();
        }
        if (base + t < n) off[base + t + 1] = carry + sh[t];
        __syncthreads();
        if (t == 0) carry += sh[1023];
        __syncthreads();
    }
}
__global__ void k_scatter(const int* __restrict__ dst, const int* __restrict__ off,
                          int* __restrict__ cur, int* __restrict__ eid) {
    int e = blockIdx.x * blockDim.x + threadIdx.x;
    if (e >= EE) return;
    int d = dst[e];
    int p = atomicAdd(&cur[d], 1);
    eid[off[d] + p] = e;
}

// ---------------- layer-3 tiny GEMM (BN inline, fp32) ----------------
__global__ __launch_bounds__(128) void k_gemm_small(
    const float* __restrict__ h, const float* __restrict__ scale,
    const float* __restrict__ shift,
    const float* __restrict__ lw, const float* __restrict__ wg,
    float* __restrict__ lin, float* __restrict__ hg)
{
    int n = blockIdx.x, t = threadIdx.x;
    const float* hr = h + (size_t)n * HIDD;
    float a0 = 0, a1 = 0, a2 = 0, a3 = 0;
    for (int k = t; k < HIDD; k += 128) {
        float a = hr[k] * scale[k] + shift[k];
        a0 += a * lw[k * 2];
        a1 += a * lw[k * 2 + 1];
        a2 += a * wg[k * 2];
        a3 += a * wg[k * 2 + 1];
    }
#pragma unroll
    for (int s = 16; s; s >>= 1) {
        a0 += __shfl_down_sync(0xFFFFFFFFu, a0, s);
        a1 += __shfl_down_sync(0xFFFFFFFFu, a1, s);
        a2 += __shfl_down_sync(0xFFFFFFFFu, a2, s);
        a3 += __shfl_down_sync(0xFFFFFFFFu, a3, s);
    }
    __shared__ float sm[4][4];
    if ((t & 31) == 0) {
        sm[t >> 5][0] = a0; sm[t >> 5][1] = a1; sm[t >> 5][2] = a2; sm[t >> 5][3] = a3;
    }
    __syncthreads();
    if (t == 0) {
        lin[(size_t)n * 2]     = sm[0][0] + sm[1][0] + sm[2][0] + sm[3][0];
        lin[(size_t)n * 2 + 1] = sm[0][1] + sm[1][1] + sm[2][1] + sm[3][1];
        hg [(size_t)n * 2]     = sm[0][2] + sm[1][2] + sm[2][2] + sm[3][2];
        hg [(size_t)n * 2 + 1] = sm[0][3] + sm[1][3] + sm[2][3] + sm[3][3];
    }
}

// ---------------- GAT pieces ----------------
__global__ void k_ve(const float* __restrict__ We, const float* __restrict__ attn,
                     float* __restrict__ ve, int H, int O) {
    int t = threadIdx.x;
    if (t >= H * EDK) return;
    int h = t / EDK, k = t % EDK;
    const float* a2 = attn + (size_t)(2 * H + h) * O;
    const float* w = We + (size_t)k * H * O + (size_t)h * O;
    float s = 0.f;
    for (int d = 0; d < O; d++) s += w[d] * a2[d];
    ve[k * H + h] = s;
}

__global__ void k_sdots(const float* __restrict__ hg, const float* __restrict__ attn,
                        float* __restrict__ ssrc, float* __restrict__ sdst, int H, int O) {
    int gw = (blockIdx.x * blockDim.x + threadIdx.x) >> 5;
    int lane = threadIdx.x & 31;
    if (gw >= NN * H) return;
    int n = gw / H, h = gw % H;
    const float* hr = hg + (size_t)n * H * O + (size_t)h * O;
    const float* a0 = attn + (size_t)h * O;
    const float* a1 = attn + (size_t)(H + h) * O;
    float d0 = 0.f, d1 = 0.f;
    for (int d = lane; d < O; d += 32) {
        float v = hr[d];
        d0 += v * a0[d];
        d1 += v * a1[d];
    }
#pragma unroll
    for (int s = 16; s; s >>= 1) {
        d0 += __shfl_down_sync(0xFFFFFFFFu, d0, s);
        d1 += __shfl_down_sync(0xFFFFFFFFu, d1, s);
    }
    if (lane == 0) { ssrc[gw] = d0; sdst[gw] = d1; }
}

__global__ void k_logits(const int* __restrict__ ei, const float* __restrict__ ea,
                         const float* __restrict__ ssrc, const float* __restrict__ sdst,
                         const float* __restrict__ ve, const float* __restrict__ at,
                         float* __restrict__ logw, int H) {
    int idx = blockIdx.x * blockDim.x + threadIdx.x;
    if (idx >= EE * H) return;
    int e = idx / H, h = idx % H;
    int s = ei[e], d = ei[EE + e];
    const float* row = ea + (size_t)e * EAC;
    float t = row[0];
    float se = 0.f;
#pragma unroll
    for (int k = 0; k < EDK; k++) se += row[1 + k] * ve[k * H + h];
    float l = ssrc[s * H + h] + sdst[d * H + h] + se + t * at[h];
    logw[idx] = (l > 0.f) ? l : 0.2f * l;
}

__global__ void k_softmax4(const int* __restrict__ off, const int* __restrict__ eid,
                           float4* __restrict__ w4) {
    int n = blockIdx.x * blockDim.x + threadIdx.x;
    if (n >= NN) return;
    int d0 = off[n], d1 = off[n + 1];
    if (d0 == d1) return;
    float4 m = make_float4(-INFINITY, -INFINITY, -INFINITY, -INFINITY);
    for (int i = d0; i < d1; i++) {
        float4 v = w4[eid[i]];
        m.x = fmaxf(m.x, v.x); m.y = fmaxf(m.y, v.y);
        m.z = fmaxf(m.z, v.z); m.w = fmaxf(m.w, v.w);
    }
    float4 s = make_float4(0.f, 0.f, 0.f, 0.f);
    for (int i = d0; i < d1; i++) {
        float4 v = w4[eid[i]];
        v.x = expf(v.x - m.x); v.y = expf(v.y - m.y);
        v.z = expf(v.z - m.z); v.w = expf(v.w - m.w);
        w4[eid[i]] = v;
        s.x += v.x; s.y += v.y; s.z += v.z; s.w += v.w;
    }
    float4 inv = make_float4(1.f / (s.x + 1e-16f), 1.f / (s.y + 1e-16f),
                             1.f / (s.z + 1e-16f), 1.f / (s.w + 1e-16f));
    for (int i = d0; i < d1; i++) {
        float4 v = w4[eid[i]];
        v.x *= inv.x; v.y *= inv.y; v.z *= inv.z; v.w *= inv.w;
        w4[eid[i]] = v;
    }
}

__global__ void k_softmax1(const int* __restrict__ off, const int* __restrict__ eid,
                           float* __restrict__ logw) {
    int n = blockIdx.x * blockDim.x + threadIdx.x;
    if (n >= NN) return;
    int d0 = off[n], d1 = off[n + 1];
    if (d0 == d1) return;
    float m = -INFINITY;
    for (int i = d0; i < d1; i++) m = fmaxf(m, logw[eid[i]]);
    float s = 0.f;
    for (int i = d0; i < d1; i++) {
        float p = expf(logw[eid[i]] - m);
        logw[eid[i]] = p;
        s += p;
    }
    float inv = 1.f / (s + 1e-16f);
    for (int i = d0; i < d1; i++) logw[eid[i]] *= inv;
}

__global__ __launch_bounds__(256) void k_agg_big(
    const float* __restrict__ hg, const float* __restrict__ w,
    const int* __restrict__ off, const int* __restrict__ eid,
    const float* __restrict__ ea, const int* __restrict__ src,
    const float* __restrict__ We, const float* __restrict__ lin,
    const float* __restrict__ lb, const float* __restrict__ cb,
    float* __restrict__ out)
{
    int n = blockIdx.x;
    int t = threadIdx.x;
    __shared__ float qs[40];
    if (t < 40) qs[t] = 0.f;
    float acc0 = 0.f, acc1 = 0.f, acc2 = 0.f, acc3 = 0.f;
    int d0 = off[n], d1 = off[n + 1];
    for (int i = d0; i < d1; i++) {
        int e = eid[i];
        int s = src[e];
        float4 wv = *(const float4*)(w + (size_t)e * 4);
        const float* hr = hg + (size_t)s * 1024;
        acc0 += wv.x * hr[t];
        acc1 += wv.y * hr[t + 256];
        acc2 += wv.z * hr[t + 512];
        acc3 += wv.w * hr[t + 768];
        if (t < 40) {
            int h = t / 10, k = t % 10;
            float wh = (h == 0) ? wv.x : (h == 1) ? wv.y : (h == 2) ? wv.z : wv.w;
            qs[t] += wh * ea[(size_t)e * EAC + 1 + k];
        }
    }
    __syncthreads();
    float acch[4] = {acc0, acc1, acc2, acc3};
#pragma unroll
    for (int h = 0; h < 4; h++) {
        int f = h * 256 + t;
        float et = 0.f;
#pragma unroll
        for (int k = 0; k < 10; k++) et += qs[h * 10 + k] * We[k * 1024 + f];
        float v = lin[(size_t)n * 1024 + f] + lb[f] + cb[f] + acch[h] + et;
        out[(size_t)n * 1024 + f] = fmaxf(v, 0.f);
    }
}

__global__ void k_agg_small(
    const float* __restrict__ hg, const float* __restrict__ w,
    const int* __restrict__ off, const int* __restrict__ eid,
    const float* __restrict__ ea, const int* __restrict__ src,
    const float* __restrict__ We, const float* __restrict__ lin,
    const float* __restrict__ lb, const float* __restrict__ cb,
    float* __restrict__ out)
{
    int n = blockIdx.x * blockDim.x + threadIdx.x;
    if (n >= NN) return;
    float a0 = 0.f, a1 = 0.f;
    float q[10];
#pragma unroll
    for (int k = 0; k < 10; k++) q[k] = 0.f;
    int d0 = off[n], d1 = off[n + 1];
    for (int i = d0; i < d1; i++) {
        int e = eid[i];
        int s = src[e];
        float wv = w[e];
        a0 += wv * hg[(size_t)s * 2];
        a1 += wv * hg[(size_t)s * 2 + 1];
        const float* row = ea + (size_t)e * EAC;
#pragma unroll
        for (int k = 0; k < 10; k++) q[k] += wv * row[1 + k];
    }
    float e0 = 0.f, e1 = 0.f;
#pragma unroll
    for (int k = 0; k < 10; k++) { e0 += q[k] * We[k * 2]; e1 += q[k] * We[k * 2 + 1]; }
    float v0 = lin[(size_t)n * 2] + lb[0] + cb[0] + a0 + e0;
    float v1 = lin[(size_t)n * 2 + 1] + lb[1] + cb[1] + a1 + e1;
    out[(size_t)n * 2] = fmaxf(v0, 0.f);
    out[(size_t)n * 2 + 1] = fmaxf(v1, 0.f);
}

// ---------------- host driver ----------------
static inline int cdiv(int a, int b) { return (a + b - 1) / b; }

struct Scratch {
    float *lin, *hg, *h, *logw, *ssrc, *sdst, *scale, *shift, *ve, *p1, *p2;
    int *deg, *off, *cur, *eid;
    __nv_bfloat16 *Ah, *Al, *B1h, *B1l, *B2h, *B2l;
};

extern "C" void kernel_launch(void* const* d_in, const int* in_sizes, int n_in,
                              void* d_out, int out_size)
{
    const float* x  = (const float*)d_in[0];
    const int*   ei = (const int*)d_in[1];
    const float* ea = (const float*)d_in[2];

    const float *Wg[3], *We[3], *attn[3], *at[3], *cb[3];
    const float *lw[3], *lb[3], *gg[3], *bb[3];

    if (in_sizes[8] == 1048576) {
        for (int i = 0; i < 3; i++) {
            Wg[i]   = (const float*)d_in[3 + 5 * i];
            We[i]   = (const float*)d_in[4 + 5 * i];
            attn[i] = (const float*)d_in[5 + 5 * i];
            at[i]   = (const float*)d_in[6 + 5 * i];
            cb[i]   = (const float*)d_in[7 + 5 * i];
            lw[i]   = (const float*)d_in[18 + 4 * i];
            lb[i]   = (const float*)d_in[19 + 4 * i];
            gg[i]   = (const float*)d_in[20 + 4 * i];
            bb[i]   = (const float*)d_in[21 + 4 * i];
        }
    } else {
        for (int i = 0; i < 3; i++) {
            Wg[i]   = (const float*)d_in[3 + 9 * i];
            We[i]   = (const float*)d_in[4 + 9 * i];
            attn[i] = (const float*)d_in[5 + 9 * i];
            at[i]   = (const float*)d_in[6 + 9 * i];
            cb[i]   = (const float*)d_in[7 + 9 * i];
            lw[i]   = (const float*)d_in[8 + 9 * i];
            lb[i]   = (const float*)d_in[9 + 9 * i];
            gg[i]   = (const float*)d_in[10 + 9 * i];
            bb[i]   = (const float*)d_in[11 + 9 * i];
        }
    }

    Scratch S;
    cudaGetSymbolAddress((void**)&S.lin, g_lin);
    cudaGetSymbolAddress((void**)&S.hg, g_hg);
    cudaGetSymbolAddress((void**)&S.h, g_h);
    cudaGetSymbolAddress((void**)&S.logw, g_logw);
    cudaGetSymbolAddress((void**)&S.ssrc, g_ssrc);
    cudaGetSymbolAddress((void**)&S.sdst, g_sdst);
    cudaGetSymbolAddress((void**)&S.p1, g_part1);
    cudaGetSymbolAddress((void**)&S.p2, g_part2);
    cudaGetSymbolAddress((void**)&S.scale, g_scale);
    cudaGetSymbolAddress((void**)&S.shift, g_shift);
    cudaGetSymbolAddress((void**)&S.ve, g_ve);
    cudaGetSymbolAddress((void**)&S.deg, g_deg);
    cudaGetSymbolAddress((void**)&S.off, g_off);
    cudaGetSymbolAddress((void**)&S.cur, g_cur);
    cudaGetSymbolAddress((void**)&S.eid, g_eid);
    cudaGetSymbolAddress((void**)&S.Ah, g_Ah);
    cudaGetSymbolAddress((void**)&S.Al, g_Al);
    cudaGetSymbolAddress((void**)&S.B1h, g_B1h);
    cudaGetSymbolAddress((void**)&S.B1l, g_B1l);
    cudaGetSymbolAddress((void**)&S.B2h, g_B2h);
    cudaGetSymbolAddress((void**)&S.B2l, g_B2l);

    cudaFuncSetAttribute(gemm_mma, cudaFuncAttributeMaxDynamicSharedMemorySize, GT_SMEM);

    // ======== layer 1 (GEMM is the 4th launch -> profiled) ========
    {
        int F = F1, Kp = 192;
        k_bnstat<<<dim3(cdiv(F, 256), BNCH), 256>>>(x, S.p1, S.p2, F);
        k_bnfin<<<cdiv(F, 256), 256>>>(S.p1, S.p2, gg[0], bb[0], S.scale, S.shift, F);
        size_t tp = (size_t)NN * Kp + 2 * (size_t)HIDD * Kp;
        k_prep<<<(int)((tp + 255) / 256), 256>>>(x, S.scale, S.shift, S.Ah, S.Al,
                                                 lw[0], Wg[0], S.B1h, S.B1l, S.B2h, S.B2l, F, Kp);
        gemm_mma<<<dim3(8, cdiv(NN, 128)), 256, GT_SMEM>>>(
            S.Ah, S.Al, Kp, S.B1h, S.B1l, S.B2h, S.B2l, S.lin, S.hg, NN);
        // CSR build (needed from softmax on)
        k_init<<<cdiv(NN, 256), 256>>>(S.deg, S.cur);
        k_hist<<<cdiv(EE, 256), 256>>>(ei + EE, S.deg);
        k_scan<<<1, 1024>>>(S.deg, S.off, NN);
        k_scatter<<<cdiv(EE, 256), 256>>>(ei + EE, S.off, S.cur, S.eid);
        k_ve<<<1, 64>>>(We[0], attn[0], S.ve, 4, 256);
        k_sdots<<<cdiv(NN * 4 * 32, 256), 256>>>(S.hg, attn[0], S.ssrc, S.sdst, 4, 256);
        k_logits<<<cdiv(EE * 4, 256), 256>>>(ei, ea, S.ssrc, S.sdst, S.ve, at[0], S.logw, 4);
        k_softmax4<<<cdiv(NN, 256), 256>>>(S.off, S.eid, (float4*)S.logw);
        k_agg_big<<<NN, 256>>>(S.hg, S.logw, S.off, S.eid, ea, ei, We[0], S.lin, lb[0], cb[0], S.h);
    }
    // ======== layer 2 ========
    {
        int F = HIDD, Kp = HIDD;
        k_bnstat<<<dim3(cdiv(F, 256), BNCH), 256>>>(S.h, S.p1, S.p2, F);
        k_bnfin<<<cdiv(F, 256), 256>>>(S.p1, S.p2, gg[1], bb[1], S.scale, S.shift, F);
        size_t tp = (size_t)NN * Kp + 2 * (size_t)HIDD * Kp;
        k_prep<<<(int)((tp + 255) / 256), 256>>>(S.h, S.scale, S.shift, S.Ah, S.Al,
                                                 lw[1], Wg[1], S.B1h, S.B1l, S.B2h, S.B2l, F, Kp);
        gemm_mma<<<dim3(8, cdiv(NN, 128)), 256, GT_SMEM>>>(
            S.Ah, S.Al, Kp, S.B1h, S.B1l, S.B2h, S.B2l, S.lin, S.hg, NN);
        k_ve<<<1, 64>>>(We[1], attn[1], S.ve, 4, 256);
        k_sdots<<<cdiv(NN * 4 * 32, 256), 256>>>(S.hg, attn[1], S.ssrc, S.sdst, 4, 256);
        k_logits<<<cdiv(EE * 4, 256), 256>>>(ei, ea, S.ssrc, S.sdst, S.ve, at[1], S.logw, 4);
        k_softmax4<<<cdiv(NN, 256), 256>>>(S.off, S.eid, (float4*)S.logw);
        k_agg_big<<<NN, 256>>>(S.hg, S.logw, S.off, S.eid, ea, ei, We[1], S.lin, lb[1], cb[1], S.h);
    }
    // ======== layer 3 ========
    {
        k_bnstat<<<dim3(cdiv(HIDD, 256), BNCH), 256>>>(S.h, S.p1, S.p2, HIDD);
        k_bnfin<<<cdiv(HIDD, 256), 256>>>(S.p1, S.p2, gg[2], bb[2], S.scale, S.shift, HIDD);
        k_gemm_small<<<NN, 128>>>(S.h, S.scale, S.shift, lw[2], Wg[2], S.lin, S.hg);
        k_ve<<<1, 64>>>(We[2], attn[2], S.ve, 1, 2);
        k_sdots<<<cdiv(NN * 1 * 32, 256), 256>>>(S.hg, attn[2], S.ssrc, S.sdst, 1, 2);
        k_logits<<<cdiv(EE * 1, 256), 256>>>(ei, ea, S.ssrc, S.sdst, S.ve, at[2], S.logw, 1);
        k_softmax1<<<cdiv(NN, 256), 256>>>(S.off, S.eid, S.logw);
        k_agg_small<<<cdiv(NN, 256), 256>>>(S.hg, S.logw, S.off, S.eid, ea, ei, We[2], S.lin, lb[2], cb[2], (float*)d_out);
    }
}

// round 9
// speedup vs baseline: 3.0911x; 1.0399x over previous
#include <cuda_runtime.h>
#include <cuda_bf16.h>
#include <cstdint>
#include <math.h>

#define NN   20000
#define EE   100000
#define F1   167
#define HIDD 1024
#define EDK  10
#define EAC  12
#define BNCH 40

// ---------------- scratch (device globals) ----------------
__device__ float g_lin[(size_t)NN * HIDD];
__device__ float g_hg [(size_t)NN * HIDD];
__device__ float g_h  [(size_t)NN * HIDD];
__device__ float g_logw[(size_t)EE * 4];
__device__ float g_ssrc[(size_t)NN * 4];
__device__ float g_sdst[(size_t)NN * 4];
__device__ float g_part1[BNCH * HIDD];
__device__ float g_part2[BNCH * HIDD];
__device__ float g_scale[HIDD];
__device__ float g_shift[HIDD];
__device__ float g_ve[EDK * 4];
__device__ int   g_deg[NN];
__device__ int   g_off[NN + 1];
__device__ int   g_cur[NN];
__device__ int   g_eid[EE];
__device__ __nv_bfloat16 g_Ah[(size_t)NN * HIDD];
__device__ __nv_bfloat16 g_Al[(size_t)NN * HIDD];
__device__ __nv_bfloat16 g_B1h[(size_t)HIDD * HIDD];
__device__ __nv_bfloat16 g_B1l[(size_t)HIDD * HIDD];
__device__ __nv_bfloat16 g_B2h[(size_t)HIDD * HIDD];
__device__ __nv_bfloat16 g_B2l[(size_t)HIDD * HIDD];

// ---------------- BatchNorm: partials (no pre-zero needed) ----------------
__global__ void k_bnstat(const float* __restrict__ x, float* __restrict__ p1,
                         float* __restrict__ p2, int F) {
    int c = blockIdx.x * blockDim.x + threadIdx.x;
    if (c >= F) return;
    int chunk = (NN + BNCH - 1) / BNCH;
    int r0 = blockIdx.y * chunk;
    int r1 = r0 + chunk; if (r1 > NN) r1 = NN;
    float a = 0.f, b = 0.f;
    for (int r = r0; r < r1; r++) {
        float v = x[(size_t)r * F + c];
        a += v; b += v * v;
    }
    p1[blockIdx.y * F + c] = a;
    p2[blockIdx.y * F + c] = b;
}

__global__ void k_bnfin(const float* __restrict__ p1, const float* __restrict__ p2,
                        const float* __restrict__ g, const float* __restrict__ b,
                        float* __restrict__ scale, float* __restrict__ shift, int F) {
    int c = blockIdx.x * blockDim.x + threadIdx.x;
    if (c >= F) return;
    float a = 0.f, s = 0.f;
    for (int y = 0; y < BNCH; y++) { a += p1[y * F + c]; s += p2[y * F + c]; }
    float invN = 1.f / (float)NN;
    float mu = a * invN;
    float var = s * invN - mu * mu;
    float rstd = rsqrtf(var + 1e-5f);
    float sc = rstd * g[c];
    scale[c] = sc;
    shift[c] = b[c] - mu * sc;
}

// ---------------- fused prep: A-split + both B-splits + zero ssrc/sdst ----------------
__global__ void k_prep(const float* __restrict__ x, const float* __restrict__ scale,
                       const float* __restrict__ shift,
                       __nv_bfloat16* __restrict__ Ah, __nv_bfloat16* __restrict__ Al,
                       const float* __restrict__ W1, const float* __restrict__ W2,
                       __nv_bfloat16* __restrict__ B1h, __nv_bfloat16* __restrict__ B1l,
                       __nv_bfloat16* __restrict__ B2h, __nv_bfloat16* __restrict__ B2l,
                       float* __restrict__ ssrc, float* __restrict__ sdst,
                       int F, int Kp) {
    size_t na = (size_t)NN * Kp;
    size_t nb = (size_t)HIDD * Kp;
    size_t i = (size_t)blockIdx.x * blockDim.x + threadIdx.x;
    if (i < na) {
        int m = (int)(i / Kp), k = (int)(i % Kp);
        float v = 0.f;
        if (k < F) v = x[(size_t)m * F + k] * scale[k] + shift[k];
        __nv_bfloat16 h = __float2bfloat16(v);
        Ah[i] = h;
        Al[i] = __float2bfloat16(v - __bfloat162float(h));
    } else if (i < na + 2 * nb) {
        size_t j = i - na;
        const float* W = (j < nb) ? W1 : W2;
        __nv_bfloat16* Bh = (j < nb) ? B1h : B2h;
        __nv_bfloat16* Bl = (j < nb) ? B1l : B2l;
        if (j >= nb) j -= nb;
        int n = (int)(j / Kp), k = (int)(j % Kp);
        float v = (k < F) ? W[(size_t)k * HIDD + n] : 0.f;
        __nv_bfloat16 h = __float2bfloat16(v);
        Bh[j] = h;
        Bl[j] = __float2bfloat16(v - __bfloat162float(h));
    } else if (i < na + 2 * nb + (size_t)NN * 4) {
        ssrc[i - na - 2 * nb] = 0.f;
    } else if (i < na + 2 * nb + (size_t)NN * 8) {
        sdst[i - na - 2 * nb - (size_t)NN * 4] = 0.f;
    }
}

// ---------------- mma.sync helpers ----------------
__device__ __forceinline__ uint32_t smem_u32(const void* p) {
    uint32_t a;
    asm("{ .reg .u64 t; cvta.to.shared.u64 t, %1; cvt.u32.u64 %0, t; }" : "=r"(a) : "l"(p));
    return a;
}
__device__ __forceinline__ void sts128(uint32_t addr, uint4 v) {
    asm volatile("st.shared.v4.b32 [%0], {%1,%2,%3,%4};"
                 :: "r"(addr), "r"(v.x), "r"(v.y), "r"(v.z), "r"(v.w) : "memory");
}
__device__ __forceinline__ void cpasync16(uint32_t s, const void* g) {
    asm volatile("cp.async.cg.shared.global [%0], [%1], 16;" :: "r"(s), "l"(g));
}
#define CP_COMMIT() asm volatile("cp.async.commit_group;" ::: "memory")
#define CP_WAIT0()  asm volatile("cp.async.wait_group 0;" ::: "memory")
#define SWZ(x) ((x) ^ (((x) >> 3) & 0x70))

#define LDSM4(r0, r1, r2, r3, addr) \
    asm volatile("ldmatrix.sync.aligned.m8n8.x4.shared.b16 {%0,%1,%2,%3}, [%4];" \
                 : "=r"(r0), "=r"(r1), "=r"(r2), "=r"(r3) : "r"(addr))

#define MMA_BF16(d, a0, a1, a2, a3, b0, b1) \
    asm volatile("mma.sync.aligned.m16n8k16.row.col.f32.bf16.bf16.f32 " \
                 "{%0,%1,%2,%3}, {%4,%5,%6,%7}, {%8,%9}, {%0,%1,%2,%3};" \
                 : "+f"((d)[0]), "+f"((d)[1]), "+f"((d)[2]), "+f"((d)[3]) \
                 : "r"(a0), "r"(a1), "r"(a2), "r"(a3), "r"(b0), "r"(b1))

// ---------------- split-bf16 GEMM: 128x256 CTA tile, 2-stage pipeline ----------------
// grid.x = 8 n-tiles: 0-3 -> (B1 -> C1), 4-7 -> (B2 -> C2, + fused attn dots). C = A @ B^T.
#define STAGE_BYTES 98304   // A: 2*16KB, B: 2*32KB
#define GT_SMEM (2 * STAGE_BYTES + 1024)

__global__ __launch_bounds__(256, 1) void gemm_mma(
    const __nv_bfloat16* __restrict__ Ah, const __nv_bfloat16* __restrict__ Al, int Kp,
    const __nv_bfloat16* __restrict__ B1h, const __nv_bfloat16* __restrict__ B1l,
    const __nv_bfloat16* __restrict__ B2h, const __nv_bfloat16* __restrict__ B2l,
    float* __restrict__ C1, float* __restrict__ C2, int M,
    const float* __restrict__ attn, float* __restrict__ ssrc, float* __restrict__ sdst)
{
    extern __shared__ char smraw[];
    uint32_t sb = (smem_u32(smraw) + 1023) & ~1023u;
    int tid = threadIdx.x, lane = tid & 31, wid = tid >> 5;
    int nt = blockIdx.x, mt = blockIdx.y;

    const __nv_bfloat16 *Bh, *Bl;
    float* C;
    int coloff;
    if (nt < 4) { Bh = B1h; Bl = B1l; C = C1; coloff = nt * 256; }
    else        { Bh = B2h; Bl = B2l; C = C2; coloff = (nt - 4) * 256; }

    int wm = wid & 1, wn = wid >> 1;   // 2 x 4 warp grid; warp tile 64x64

    float acc[4][8][4];
#pragma unroll
    for (int a = 0; a < 4; a++)
#pragma unroll
        for (int b = 0; b < 8; b++)
#pragma unroll
            for (int cc = 0; cc < 4; cc++) acc[a][b][cc] = 0.f;

    // raw (un-swizzled) ldmatrix base offsets for k16=0; add k16*32 then swizzle
    uint32_t rawA[4];   // [mi]
    uint32_t rawB[4];   // [pp]
#pragma unroll
    for (int mi = 0; mi < 4; mi++) {
        int row = wm * 64 + mi * 16 + (lane & 15);
        rawA[mi] = (uint32_t)(row * 128 + (lane >> 4) * 16);
    }
#pragma unroll
    for (int p = 0; p < 4; p++) {
        int row = wn * 64 + p * 16 + ((lane >> 4) << 3) + (lane & 7);
        rawB[p] = (uint32_t)(row * 128 + (((lane >> 3) & 1) << 4));
    }

    int q = tid & 7;
    int rr = tid >> 3;
    int chunks = Kp >> 6;

    auto load_stage = [&](int c) {
        uint32_t base = sb + (uint32_t)(c & 1) * STAGE_BYTES;
        uint32_t bAh = base, bAl = base + 16384, bBh = base + 32768, bBl = base + 65536;
        size_t kel = (size_t)c * 64 + q * 8;
#pragma unroll
        for (int i = 0; i < 4; i++) {
            int row = rr + i * 32;
            uint32_t soff = SWZ((uint32_t)(row * 128 + q * 16));
            int m = mt * 128 + row;
            if (m < M) {
                cpasync16(bAh + soff, Ah + (size_t)m * Kp + kel);
                cpasync16(bAl + soff, Al + (size_t)m * Kp + kel);
            } else {
                uint4 z = make_uint4(0, 0, 0, 0);
                sts128(bAh + soff, z);
                sts128(bAl + soff, z);
            }
        }
#pragma unroll
        for (int i = 0; i < 8; i++) {
            int row = rr + i * 32;
            uint32_t soff = SWZ((uint32_t)(row * 128 + q * 16));
            int nr = coloff + row;
            cpasync16(bBh + soff, Bh + (size_t)nr * Kp + kel);
            cpasync16(bBl + soff, Bl + (size_t)nr * Kp + kel);
        }
        CP_COMMIT();
    };

    load_stage(0);

    for (int c = 0; c < chunks; c++) {
        CP_WAIT0();
        __syncthreads();                 // stage c ready; buffer (c+1)&1 free
        if (c + 1 < chunks) load_stage(c + 1);

        uint32_t cur = sb + (uint32_t)(c & 1) * STAGE_BYTES;
        uint32_t cAh = cur, cAl = cur + 16384, cBh = cur + 32768, cBl = cur + 65536;
#pragma unroll 1
        for (int k16 = 0; k16 < 4; k16++) {
            uint32_t kb = (uint32_t)k16 * 32;
            uint32_t bh0[8], bh1[8], bl0[8], bl1[8];
#pragma unroll
            for (int pp = 0; pp < 4; pp++) {
                uint32_t addr = SWZ(rawB[pp] + kb);
                uint32_t r0_, r1_, r2_, r3_;
                LDSM4(r0_, r1_, r2_, r3_, cBh + addr);
                bh0[pp * 2] = r0_; bh1[pp * 2] = r1_;
                bh0[pp * 2 + 1] = r2_; bh1[pp * 2 + 1] = r3_;
                LDSM4(r0_, r1_, r2_, r3_, cBl + addr);
                bl0[pp * 2] = r0_; bl1[pp * 2] = r1_;
                bl0[pp * 2 + 1] = r2_; bl1[pp * 2 + 1] = r3_;
            }
#pragma unroll
            for (int mi = 0; mi < 4; mi++) {
                uint32_t addr = SWZ(rawA[mi] + kb);
                uint32_t a0, a1, a2, a3, l0, l1, l2, l3;
                LDSM4(a0, a1, a2, a3, cAh + addr);
                LDSM4(l0, l1, l2, l3, cAl + addr);
#pragma unroll
                for (int ni = 0; ni < 8; ni++) {
                    MMA_BF16(acc[mi][ni], a0, a1, a2, a3, bh0[ni], bh1[ni]);
                    MMA_BF16(acc[mi][ni], a0, a1, a2, a3, bl0[ni], bl1[ni]);
                    MMA_BF16(acc[mi][ni], l0, l1, l2, l3, bh0[ni], bh1[ni]);
                }
            }
        }
    }

    // epilogue: stores + fused s_src/s_dst dots for the hg half (nt>=4)
    int doAttn = (nt >= 4);
    int hh = nt - 4;
    const float* a0p = attn + (size_t)hh * 256;
    const float* a1p = attn + (size_t)(4 + hh) * 256;
#pragma unroll
    for (int mi = 0; mi < 4; mi++) {
        int gr = mt * 128 + wm * 64 + mi * 16 + (lane >> 2);
        float s0 = 0.f, d0 = 0.f, s1 = 0.f, d1 = 0.f;
#pragma unroll
        for (int ni = 0; ni < 8; ni++) {
            int cw = wn * 64 + ni * 8 + ((lane & 3) << 1);   // col within head
            int gc = coloff + cw;
            if (gr < M)
                *(float2*)(C + (size_t)gr * HIDD + gc) = make_float2(acc[mi][ni][0], acc[mi][ni][1]);
            if (gr + 8 < M)
                *(float2*)(C + (size_t)(gr + 8) * HIDD + gc) = make_float2(acc[mi][ni][2], acc[mi][ni][3]);
            if (doAttn) {
                float2 av = *(const float2*)(a0p + cw);
                float2 bv = *(const float2*)(a1p + cw);
                s0 += acc[mi][ni][0] * av.x + acc[mi][ni][1] * av.y;
                d0 += acc[mi][ni][0] * bv.x + acc[mi][ni][1] * bv.y;
                s1 += acc[mi][ni][2] * av.x + acc[mi][ni][3] * av.y;
                d1 += acc[mi][ni][2] * bv.x + acc[mi][ni][3] * bv.y;
            }
        }
        if (doAttn) {
#pragma unroll
            for (int o = 1; o < 4; o <<= 1) {
                s0 += __shfl_xor_sync(0xFFFFFFFFu, s0, o);
                d0 += __shfl_xor_sync(0xFFFFFFFFu, d0, o);
                s1 += __shfl_xor_sync(0xFFFFFFFFu, s1, o);
                d1 += __shfl_xor_sync(0xFFFFFFFFu, d1, o);
            }
            if ((lane & 3) == 0) {
                if (gr < M) {
                    atomicAdd(&ssrc[gr * 4 + hh], s0);
                    atomicAdd(&sdst[gr * 4 + hh], d0);
                }
                if (gr + 8 < M) {
                    atomicAdd(&ssrc[(gr + 8) * 4 + hh], s1);
                    atomicAdd(&sdst[(gr + 8) * 4 + hh], d1);
                }
            }
        }
    }
}

// ---------------- CSR build ----------------
__global__ void k_init(int* deg, int* cur) {
    int i = blockIdx.x * blockDim.x + threadIdx.x;
    if (i < NN) { deg[i] = 0; cur[i] = 0; }
}
__global__ void k_hist(const int* __restrict__ dst, int* __restrict__ deg) {
    int e = blockIdx.x * blockDim.x + threadIdx.x;
    if (e < EE) atomicAdd(&deg[dst[e]], 1);
}
__global__ void k_scan(const int* __restrict__ deg, int* __restrict__ off, int n) {
    __shared__ int sh[1024];
    __shared__ int carry;
    int t = threadIdx.x;
    if (t == 0) { carry = 0; off[0] = 0; }
    __syncthreads();
    for (int base = 0; base < n; base += 1024) {
        int v = (base + t < n) ? deg[base + t] : 0;
        sh[t] = v;
        __syncthreads();
        for (int d = 1; d < 1024; d <<= 1) {
            int add = (t >= d) ? sh[t - d] : 0;
            __syncthreads();
            sh[t] += add;
            __syncthreads();
        }
        if (base + t < n) off[base + t + 1] = carry + sh[t];
        __syncthreads();
        if (t == 0) carry += sh[1023];
        __syncthreads();
    }
}
__global__ void k_scatter(const int* __restrict__ dst, const int* __restrict__ off,
                          int* __restrict__ cur, int* __restrict__ eid) {
    int e = blockIdx.x * blockDim.x + threadIdx.x;
    if (e >= EE) return;
    int d = dst[e];
    int p = atomicAdd(&cur[d], 1);
    eid[off[d] + p] = e;
}

// ---------------- layer-3 tiny GEMM (BN inline, fp32) ----------------
__global__ __launch_bounds__(128) void k_gemm_small(
    const float* __restrict__ h, const float* __restrict__ scale,
    const float* __restrict__ shift,
    const float* __restrict__ lw, const float* __restrict__ wg,
    float* __restrict__ lin, float* __restrict__ hg)
{
    int n = blockIdx.x, t = threadIdx.x;
    const float* hr = h + (size_t)n * HIDD;
    float a0 = 0, a1 = 0, a2 = 0, a3 = 0;
    for (int k = t; k < HIDD; k += 128) {
        float a = hr[k] * scale[k] + shift[k];
        a0 += a * lw[k * 2];
        a1 += a * lw[k * 2 + 1];
        a2 += a * wg[k * 2];
        a3 += a * wg[k * 2 + 1];
    }
#pragma unroll
    for (int s = 16; s; s >>= 1) {
        a0 += __shfl_down_sync(0xFFFFFFFFu, a0, s);
        a1 += __shfl_down_sync(0xFFFFFFFFu, a1, s);
        a2 += __shfl_down_sync(0xFFFFFFFFu, a2, s);
        a3 += __shfl_down_sync(0xFFFFFFFFu, a3, s);
    }
    __shared__ float sm[4][4];
    if ((t & 31) == 0) {
        sm[t >> 5][0] = a0; sm[t >> 5][1] = a1; sm[t >> 5][2] = a2; sm[t >> 5][3] = a3;
    }
    __syncthreads();
    if (t == 0) {
        lin[(size_t)n * 2]     = sm[0][0] + sm[1][0] + sm[2][0] + sm[3][0];
        lin[(size_t)n * 2 + 1] = sm[0][1] + sm[1][1] + sm[2][1] + sm[3][1];
        hg [(size_t)n * 2]     = sm[0][2] + sm[1][2] + sm[2][2] + sm[3][2];
        hg [(size_t)n * 2 + 1] = sm[0][3] + sm[1][3] + sm[2][3] + sm[3][3];
    }
}

// ---------------- GAT pieces ----------------
__global__ void k_ve(const float* __restrict__ We, const float* __restrict__ attn,
                     float* __restrict__ ve, int H, int O) {
    int t = threadIdx.x;
    if (t >= H * EDK) return;
    int h = t / EDK, k = t % EDK;
    const float* a2 = attn + (size_t)(2 * H + h) * O;
    const float* w = We + (size_t)k * H * O + (size_t)h * O;
    float s = 0.f;
    for (int d = 0; d < O; d++) s += w[d] * a2[d];
    ve[k * H + h] = s;
}

__global__ void k_sdots(const float* __restrict__ hg, const float* __restrict__ attn,
                        float* __restrict__ ssrc, float* __restrict__ sdst, int H, int O) {
    int gw = (blockIdx.x * blockDim.x + threadIdx.x) >> 5;
    int lane = threadIdx.x & 31;
    if (gw >= NN * H) return;
    int n = gw / H, h = gw % H;
    const float* hr = hg + (size_t)n * H * O + (size_t)h * O;
    const float* a0 = attn + (size_t)h * O;
    const float* a1 = attn + (size_t)(H + h) * O;
    float d0 = 0.f, d1 = 0.f;
    for (int d = lane; d < O; d += 32) {
        float v = hr[d];
        d0 += v * a0[d];
        d1 += v * a1[d];
    }
#pragma unroll
    for (int s = 16; s; s >>= 1) {
        d0 += __shfl_down_sync(0xFFFFFFFFu, d0, s);
        d1 += __shfl_down_sync(0xFFFFFFFFu, d1, s);
    }
    if (lane == 0) { ssrc[gw] = d0; sdst[gw] = d1; }
}

__global__ void k_logits(const int* __restrict__ ei, const float* __restrict__ ea,
                         const float* __restrict__ ssrc, const float* __restrict__ sdst,
                         const float* __restrict__ ve, const float* __restrict__ at,
                         float* __restrict__ logw, int H) {
    int idx = blockIdx.x * blockDim.x + threadIdx.x;
    if (idx >= EE * H) return;
    int e = idx / H, h = idx % H;
    int s = ei[e], d = ei[EE + e];
    const float* row = ea + (size_t)e * EAC;
    float t = row[0];
    float se = 0.f;
#pragma unroll
    for (int k = 0; k < EDK; k++) se += row[1 + k] * ve[k * H + h];
    float l = ssrc[s * H + h] + sdst[d * H + h] + se + t * at[h];
    logw[idx] = (l > 0.f) ? l : 0.2f * l;
}

__global__ void k_softmax4(const int* __restrict__ off, const int* __restrict__ eid,
                           float4* __restrict__ w4) {
    int n = blockIdx.x * blockDim.x + threadIdx.x;
    if (n >= NN) return;
    int d0 = off[n], d1 = off[n + 1];
    if (d0 == d1) return;
    float4 m = make_float4(-INFINITY, -INFINITY, -INFINITY, -INFINITY);
    for (int i = d0; i < d1; i++) {
        float4 v = w4[eid[i]];
        m.x = fmaxf(m.x, v.x); m.y = fmaxf(m.y, v.y);
        m.z = fmaxf(m.z, v.z); m.w = fmaxf(m.w, v.w);
    }
    float4 s = make_float4(0.f, 0.f, 0.f, 0.f);
    for (int i = d0; i < d1; i++) {
        float4 v = w4[eid[i]];
        v.x = expf(v.x - m.x); v.y = expf(v.y - m.y);
        v.z = expf(v.z - m.z); v.w = expf(v.w - m.w);
        w4[eid[i]] = v;
        s.x += v.x; s.y += v.y; s.z += v.z; s.w += v.w;
    }
    float4 inv = make_float4(1.f / (s.x + 1e-16f), 1.f / (s.y + 1e-16f),
                             1.f / (s.z + 1e-16f), 1.f / (s.w + 1e-16f));
    for (int i = d0; i < d1; i++) {
        float4 v = w4[eid[i]];
        v.x *= inv.x; v.y *= inv.y; v.z *= inv.z; v.w *= inv.w;
        w4[eid[i]] = v;
    }
}

__global__ void k_softmax1(const int* __restrict__ off, const int* __restrict__ eid,
                           float* __restrict__ logw) {
    int n = blockIdx.x * blockDim.x + threadIdx.x;
    if (n >= NN) return;
    int d0 = off[n], d1 = off[n + 1];
    if (d0 == d1) return;
    float m = -INFINITY;
    for (int i = d0; i < d1; i++) m = fmaxf(m, logw[eid[i]]);
    float s = 0.f;
    for (int i = d0; i < d1; i++) {
        float p = expf(logw[eid[i]] - m);
        logw[eid[i]] = p;
        s += p;
    }
    float inv = 1.f / (s + 1e-16f);
    for (int i = d0; i < d1; i++) logw[eid[i]] *= inv;
}

__global__ __launch_bounds__(256) void k_agg_big(
    const float* __restrict__ hg, const float* __restrict__ w,
    const int* __restrict__ off, const int* __restrict__ eid,
    const float* __restrict__ ea, const int* __restrict__ src,
    const float* __restrict__ We, const float* __restrict__ lin,
    const float* __restrict__ lb, const float* __restrict__ cb,
    float* __restrict__ out)
{
    int n = blockIdx.x;
    int t = threadIdx.x;
    __shared__ float qs[40];
    if (t < 40) qs[t] = 0.f;
    float acc0 = 0.f, acc1 = 0.f, acc2 = 0.f, acc3 = 0.f;
    int d0 = off[n], d1 = off[n + 1];
    for (int i = d0; i < d1; i++) {
        int e = eid[i];
        int s = src[e];
        float4 wv = *(const float4*)(w + (size_t)e * 4);
        const float* hr = hg + (size_t)s * 1024;
        acc0 += wv.x * hr[t];
        acc1 += wv.y * hr[t + 256];
        acc2 += wv.z * hr[t + 512];
        acc3 += wv.w * hr[t + 768];
        if (t < 40) {
            int h = t / 10, k = t % 10;
            float wh = (h == 0) ? wv.x : (h == 1) ? wv.y : (h == 2) ? wv.z : wv.w;
            qs[t] += wh * ea[(size_t)e * EAC + 1 + k];
        }
    }
    __syncthreads();
    float acch[4] = {acc0, acc1, acc2, acc3};
#pragma unroll
    for (int h = 0; h < 4; h++) {
        int f = h * 256 + t;
        float et = 0.f;
#pragma unroll
        for (int k = 0; k < 10; k++) et += qs[h * 10 + k] * We[k * 1024 + f];
        float v = lin[(size_t)n * 1024 + f] + lb[f] + cb[f] + acch[h] + et;
        out[(size_t)n * 1024 + f] = fmaxf(v, 0.f);
    }
}

__global__ void k_agg_small(
    const float* __restrict__ hg, const float* __restrict__ w,
    const int* __restrict__ off, const int* __restrict__ eid,
    const float* __restrict__ ea, const int* __restrict__ src,
    const float* __restrict__ We, const float* __restrict__ lin,
    const float* __restrict__ lb, const float* __restrict__ cb,
    float* __restrict__ out)
{
    int n = blockIdx.x * blockDim.x + threadIdx.x;
    if (n >= NN) return;
    float a0 = 0.f, a1 = 0.f;
    float q[10];
#pragma unroll
    for (int k = 0; k < 10; k++) q[k] = 0.f;
    int d0 = off[n], d1 = off[n + 1];
    for (int i = d0; i < d1; i++) {
        int e = eid[i];
        int s = src[e];
        float wv = w[e];
        a0 += wv * hg[(size_t)s * 2];
        a1 += wv * hg[(size_t)s * 2 + 1];
        const float* row = ea + (size_t)e * EAC;
#pragma unroll
        for (int k = 0; k < 10; k++) q[k] += wv * row[1 + k];
    }
    float e0 = 0.f, e1 = 0.f;
#pragma unroll
    for (int k = 0; k < 10; k++) { e0 += q[k] * We[k * 2]; e1 += q[k] * We[k * 2 + 1]; }
    float v0 = lin[(size_t)n * 2] + lb[0] + cb[0] + a0 + e0;
    float v1 = lin[(size_t)n * 2 + 1] + lb[1] + cb[1] + a1 + e1;
    out[(size_t)n * 2] = fmaxf(v0, 0.f);
    out[(size_t)n * 2 + 1] = fmaxf(v1, 0.f);
}

// ---------------- host driver ----------------
static inline int cdiv(int a, int b) { return (a + b - 1) / b; }

struct Scratch {
    float *lin, *hg, *h, *logw, *ssrc, *sdst, *scale, *shift, *ve, *p1, *p2;
    int *deg, *off, *cur, *eid;
    __nv_bfloat16 *Ah, *Al, *B1h, *B1l, *B2h, *B2l;
};

extern "C" void kernel_launch(void* const* d_in, const int* in_sizes, int n_in,
                              void* d_out, int out_size)
{
    const float* x  = (const float*)d_in[0];
    const int*   ei = (const int*)d_in[1];
    const float* ea = (const float*)d_in[2];

    const float *Wg[3], *We[3], *attn[3], *at[3], *cb[3];
    const float *lw[3], *lb[3], *gg[3], *bb[3];

    if (in_sizes[8] == 1048576) {
        for (int i = 0; i < 3; i++) {
            Wg[i]   = (const float*)d_in[3 + 5 * i];
            We[i]   = (const float*)d_in[4 + 5 * i];
            attn[i] = (const float*)d_in[5 + 5 * i];
            at[i]   = (const float*)d_in[6 + 5 * i];
            cb[i]   = (const float*)d_in[7 + 5 * i];
            lw[i]   = (const float*)d_in[18 + 4 * i];
            lb[i]   = (const float*)d_in[19 + 4 * i];
            gg[i]   = (const float*)d_in[20 + 4 * i];
            bb[i]   = (const float*)d_in[21 + 4 * i];
        }
    } else {
        for (int i = 0; i < 3; i++) {
            Wg[i]   = (const float*)d_in[3 + 9 * i];
            We[i]   = (const float*)d_in[4 + 9 * i];
            attn[i] = (const float*)d_in[5 + 9 * i];
            at[i]   = (const float*)d_in[6 + 9 * i];
            cb[i]   = (const float*)d_in[7 + 9 * i];
            lw[i]   = (const float*)d_in[8 + 9 * i];
            lb[i]   = (const float*)d_in[9 + 9 * i];
            gg[i]   = (const float*)d_in[10 + 9 * i];
            bb[i]   = (const float*)d_in[11 + 9 * i];
        }
    }

    Scratch S;
    cudaGetSymbolAddress((void**)&S.lin, g_lin);
    cudaGetSymbolAddress((void**)&S.hg, g_hg);
    cudaGetSymbolAddress((void**)&S.h, g_h);
    cudaGetSymbolAddress((void**)&S.logw, g_logw);
    cudaGetSymbolAddress((void**)&S.ssrc, g_ssrc);
    cudaGetSymbolAddress((void**)&S.sdst, g_sdst);
    cudaGetSymbolAddress((void**)&S.p1, g_part1);
    cudaGetSymbolAddress((void**)&S.p2, g_part2);
    cudaGetSymbolAddress((void**)&S.scale, g_scale);
    cudaGetSymbolAddress((void**)&S.shift, g_shift);
    cudaGetSymbolAddress((void**)&S.ve, g_ve);
    cudaGetSymbolAddress((void**)&S.deg, g_deg);
    cudaGetSymbolAddress((void**)&S.off, g_off);
    cudaGetSymbolAddress((void**)&S.cur, g_cur);
    cudaGetSymbolAddress((void**)&S.eid, g_eid);
    cudaGetSymbolAddress((void**)&S.Ah, g_Ah);
    cudaGetSymbolAddress((void**)&S.Al, g_Al);
    cudaGetSymbolAddress((void**)&S.B1h, g_B1h);
    cudaGetSymbolAddress((void**)&S.B1l, g_B1l);
    cudaGetSymbolAddress((void**)&S.B2h, g_B2h);
    cudaGetSymbolAddress((void**)&S.B2l, g_B2l);

    cudaFuncSetAttribute(gemm_mma, cudaFuncAttributeMaxDynamicSharedMemorySize, GT_SMEM);

    // ======== layer 1 (GEMM is the 4th launch -> profiled) ========
    {
        int F = F1, Kp = 192;
        k_bnstat<<<dim3(cdiv(F, 256), BNCH), 256>>>(x, S.p1, S.p2, F);
        k_bnfin<<<cdiv(F, 256), 256>>>(S.p1, S.p2, gg[0], bb[0], S.scale, S.shift, F);
        size_t tp = (size_t)NN * Kp + 2 * (size_t)HIDD * Kp + (size_t)NN * 8;
        k_prep<<<(int)((tp + 255) / 256), 256>>>(x, S.scale, S.shift, S.Ah, S.Al,
                                                 lw[0], Wg[0], S.B1h, S.B1l, S.B2h, S.B2l,
                                                 S.ssrc, S.sdst, F, Kp);
        gemm_mma<<<dim3(8, cdiv(NN, 128)), 256, GT_SMEM>>>(
            S.Ah, S.Al, Kp, S.B1h, S.B1l, S.B2h, S.B2l, S.lin, S.hg, NN,
            attn[0], S.ssrc, S.sdst);
        // CSR build (needed from softmax on)
        k_init<<<cdiv(NN, 256), 256>>>(S.deg, S.cur);
        k_hist<<<cdiv(EE, 256), 256>>>(ei + EE, S.deg);
        k_scan<<<1, 1024>>>(S.deg, S.off, NN);
        k_scatter<<<cdiv(EE, 256), 256>>>(ei + EE, S.off, S.cur, S.eid);
        k_ve<<<1, 64>>>(We[0], attn[0], S.ve, 4, 256);
        k_logits<<<cdiv(EE * 4, 256), 256>>>(ei, ea, S.ssrc, S.sdst, S.ve, at[0], S.logw, 4);
        k_softmax4<<<cdiv(NN, 256), 256>>>(S.off, S.eid, (float4*)S.logw);
        k_agg_big<<<NN, 256>>>(S.hg, S.logw, S.off, S.eid, ea, ei, We[0], S.lin, lb[0], cb[0], S.h);
    }
    // ======== layer 2 ========
    {
        int F = HIDD, Kp = HIDD;
        k_bnstat<<<dim3(cdiv(F, 256), BNCH), 256>>>(S.h, S.p1, S.p2, F);
        k_bnfin<<<cdiv(F, 256), 256>>>(S.p1, S.p2, gg[1], bb[1], S.scale, S.shift, F);
        size_t tp = (size_t)NN * Kp + 2 * (size_t)HIDD * Kp + (size_t)NN * 8;
        k_prep<<<(int)((tp + 255) / 256), 256>>>(S.h, S.scale, S.shift, S.Ah, S.Al,
                                                 lw[1], Wg[1], S.B1h, S.B1l, S.B2h, S.B2l,
                                                 S.ssrc, S.sdst, F, Kp);
        gemm_mma<<<dim3(8, cdiv(NN, 128)), 256, GT_SMEM>>>(
            S.Ah, S.Al, Kp, S.B1h, S.B1l, S.B2h, S.B2l, S.lin, S.hg, NN,
            attn[1], S.ssrc, S.sdst);
        k_ve<<<1, 64>>>(We[1], attn[1], S.ve, 4, 256);
        k_logits<<<cdiv(EE * 4, 256), 256>>>(ei, ea, S.ssrc, S.sdst, S.ve, at[1], S.logw, 4);
        k_softmax4<<<cdiv(NN, 256), 256>>>(S.off, S.eid, (float4*)S.logw);
        k_agg_big<<<NN, 256>>>(S.hg, S.logw, S.off, S.eid, ea, ei, We[1], S.lin, lb[1], cb[1], S.h);
    }
    // ======== layer 3 ========
    {
        k_bnstat<<<dim3(cdiv(HIDD, 256), BNCH), 256>>>(S.h, S.p1, S.p2, HIDD);
        k_bnfin<<<cdiv(HIDD, 256), 256>>>(S.p1, S.p2, gg[2], bb[2], S.scale, S.shift, HIDD);
        k_gemm_small<<<NN, 128>>>(S.h, S.scale, S.shift, lw[2], Wg[2], S.lin, S.hg);
        k_ve<<<1, 64>>>(We[2], attn[2], S.ve, 1, 2);
        k_sdots<<<cdiv(NN * 1 * 32, 256), 256>>>(S.hg, attn[2], S.ssrc, S.sdst, 1, 2);
        k_logits<<<cdiv(EE * 1, 256), 256>>>(ei, ea, S.ssrc, S.sdst, S.ve, at[2], S.logw, 1);
        k_softmax1<<<cdiv(NN, 256), 256>>>(S.off, S.eid, S.logw);
        k_agg_small<<<cdiv(NN, 256), 256>>>(S.hg, S.logw, S.off, S.eid, ea, ei, We[2], S.lin, lb[2], cb[2], (float*)d_out);
    }
}